// round 8
// baseline (speedup 1.0000x reference)
#include <cuda_runtime.h>
#include <cstdint>

// ---------------- problem constants ----------------
#define P_TOTAL 8192
#define DDIM    256
#define E_TOTAL 8192
#define NITEMS  2048                   // 64 ptiles * 32 chunks
#define NCTA    148
#define NSLOT   4

#define ZQ_ELEMS 2097152
#define LOSS_OFF 2097152
#define IDX_OFF  2097153

// ---------------- GEMM tiling ----------------
#define BM 128
#define BN 256
#define BK 32
#define NTHREADS 512
#define TS 36
#define ROWB (TS * 4)                  // 144 B per smem row
#define A_BYTES (BM * ROWB)            // 18432
#define B_BYTES (BN * ROWB)            // 36864
#define AH_OFF 0
#define AL_OFF A_BYTES
#define BH_OFF (2 * A_BYTES)
#define BL_OFF (2 * A_BYTES + B_BYTES)
#define STAGE_BYTES (2 * A_BYTES + 2 * B_BYTES)   // 110592
#define SMEM_TOTAL (2 * STAGE_BYTES)              // 221184

// ---------------- scratch ----------------
__device__ __align__(256) float g_zhi[P_TOTAL * DDIM];   // k-permuted
__device__ __align__(256) float g_zlo[P_TOTAL * DDIM];   // k-permuted
__device__ __align__(256) float g_zl [P_TOTAL * DDIM];   // plain [p][d]
__device__ __align__(256) float g_whi[E_TOTAL * DDIM];   // k-permuted
__device__ __align__(256) float g_wlo[E_TOTAL * DDIM];   // k-permuted
__device__ __align__(256) float g_wsq[E_TOTAL];
__device__ float g_pv[NSLOT][P_TOTAL][32];
__device__ int   g_pi[NSLOT][P_TOTAL][32];
__device__ float g_blockloss[256];

// ---------------- helpers ----------------
__device__ __forceinline__ uint32_t smem_u32(const void* p) {
    uint32_t a;
    asm("{ .reg .u64 t; cvta.to.shared.u64 t, %1; cvt.u32.u64 %0, t; }" : "=r"(a) : "l"(p));
    return a;
}
#define CP16(sa, ga) \
    asm volatile("cp.async.cg.shared.global [%0], [%1], 16;" :: "r"((uint32_t)(sa)), "l"(ga))
#define CP_COMMIT() asm volatile("cp.async.commit_group;" ::: "memory")
#define CP_WAIT0()  asm volatile("cp.async.wait_group 0;" ::: "memory")

__device__ __forceinline__ float tf32r(float x) {
    uint32_t r;
    asm("cvt.rna.tf32.f32 %0, %1;" : "=r"(r) : "f"(x));
    return __uint_as_float(r);
}
__device__ __forceinline__ uint2 lds_u64(uint32_t addr) {
    uint2 v;
    asm volatile("ld.shared.v2.b32 {%0,%1}, [%2];" : "=r"(v.x), "=r"(v.y) : "r"(addr));
    return v;
}
__device__ __forceinline__ void mma_tf32(float& c0, float& c1, float& c2, float& c3,
                                         uint32_t a0, uint32_t a1, uint32_t a2, uint32_t a3,
                                         uint32_t b0, uint32_t b1) {
    asm volatile("mma.sync.aligned.m16n8k8.row.col.f32.tf32.tf32.f32 "
                 "{%0,%1,%2,%3}, {%4,%5,%6,%7}, {%8,%9}, {%0,%1,%2,%3};"
                 : "+f"(c0), "+f"(c1), "+f"(c2), "+f"(c3)
                 : "r"(a0), "r"(a1), "r"(a2), "r"(a3), "r"(b0), "r"(b1));
}
__device__ __forceinline__ int dperm(int d) {
    return ((d >> 3) << 3) + ((d & 3) << 1) + ((d >> 2) & 1);
}

// ---------------- Stage A1: z -> (z_hi, z_lo) permuted + plain + partial init ----
__global__ void vq_prep_z(const float* __restrict__ z) {
    int idx = blockIdx.x * 256 + threadIdx.x;
    float v = z[idx];
    int n = idx >> 20, rem = idx & 1048575;
    int d = rem >> 12, thw = rem & 4095;
    int p = (n << 12) + thw;
    float hi = tf32r(v);
    int op = p * DDIM + dperm(d);
    g_zhi[op] = hi;
    g_zlo[op] = tf32r(v - hi);
    g_zl[p * DDIM + d] = v;
    if (idx < NSLOT * P_TOTAL * 32) {
        ((float*)g_pv)[idx] = __int_as_float(0x7f800000);
        ((int*)g_pi)[idx] = 0;
    }
}

// ---------------- Stage A2: w -> (w_hi, w_lo) permuted ----------------
__global__ void vq_prep_w(const float* __restrict__ w) {
    int idx = blockIdx.x * 256 + threadIdx.x;
    float v = w[idx];
    int e = idx >> 8, d = idx & 255;
    float hi = tf32r(v);
    int op = e * DDIM + dperm(d);
    g_whi[op] = hi;
    g_wlo[op] = tf32r(v - hi);
}

// ---------------- Stage A3: ||w_e||^2 ----------------
__global__ void vq_wsq(const float* __restrict__ w) {
    int gwarp = (blockIdx.x * blockDim.x + threadIdx.x) >> 5;
    int lane = threadIdx.x & 31;
    const float* row = w + (size_t)gwarp * DDIM;
    float4 a = *(const float4*)&row[lane * 4];
    float4 b = *(const float4*)&row[128 + lane * 4];
    float s = a.x*a.x + a.y*a.y + a.z*a.z + a.w*a.w
            + b.x*b.x + b.y*b.y + b.z*b.z + b.w*b.w;
    #pragma unroll
    for (int off = 16; off >= 1; off >>= 1)
        s += __shfl_down_sync(0xffffffffu, s, off);
    if (lane == 0) g_wsq[gwarp] = s;
}

// ---------------- Stage B: persistent fused 3xTF32 distance GEMM + argmin ------
__global__ __launch_bounds__(NTHREADS, 1)
void vq_mma() {
    extern __shared__ float sm[];
    const uint32_t sb = smem_u32(sm);

    const int t = threadIdx.x;
    const int lane = t & 31, wid = t >> 5;
    const int warpM = wid >> 3;          // 0..1
    const int warpN = wid & 7;           // 0..7
    const int g = lane >> 2;             // 0..7
    const int tg = lane & 3;             // 0..3
    const int bid = blockIdx.x;
    const int slot = bid & 3;
    const uint32_t koff_tg = tg * 8;

    // exact-tiling work ranges
    const int itlo = (bid * NITEMS) / NCTA;
    const int ithi = ((bid + 1) * NITEMS) / NCTA;
    const int nsteps = (ithi - itlo) * 8;

    // loader per-thread constants (512 threads: 64 rows x 8 quad-cols)
    const int lr0 = t >> 3;              // 0..63
    const int lqc = t & 7;               // 0..7
    const uint32_t sm_a = (uint32_t)(lr0 * ROWB + lqc * 16);
    const size_t toff = (size_t)lr0 * DDIM + lqc * 4;

    // ---- incremental loader state (prefetch cursor) ----
    const float* pAh = g_zhi + (size_t)(itlo >> 5) * BM * DDIM + toff;
    const float* pAl = g_zlo + (size_t)(itlo >> 5) * BM * DDIM + toff;
    const float* pBh = g_whi + (size_t)(itlo & 31) * BN * DDIM + toff;
    const float* pBl = g_wlo + (size_t)(itlo & 31) * BN * DDIM + toff;
    int nextk = 0;                        // float offset within row (0,32,...,224)
    int nchunk = itlo & 31;
    uint32_t lstage = sb + sm_a;          // toggles between the two stages
    int lsgn = STAGE_BYTES;               // add-toggle (XOR wrong: unaligned base)

    auto issue_load = [&]() {
        const float* ah = pAh + nextk;
        const float* al = pAl + nextk;
        const float* bh = pBh + nextk;
        const float* bl = pBl + nextk;
        const uint32_t base = lstage;
        #pragma unroll
        for (int i = 0; i < 2; i++)
            CP16(base + AH_OFF + i * 64 * ROWB, ah + (size_t)i * 64 * DDIM);
        #pragma unroll
        for (int i = 0; i < 2; i++)
            CP16(base + AL_OFF + i * 64 * ROWB, al + (size_t)i * 64 * DDIM);
        #pragma unroll
        for (int i = 0; i < 4; i++)
            CP16(base + BH_OFF + i * 64 * ROWB, bh + (size_t)i * 64 * DDIM);
        #pragma unroll
        for (int i = 0; i < 4; i++)
            CP16(base + BL_OFF + i * 64 * ROWB, bl + (size_t)i * 64 * DDIM);
        CP_COMMIT();
        // advance cursor
        lstage += lsgn; lsgn = -lsgn;
        nextk += 32;
        if (nextk == 256) {
            nextk = 0;
            pBh += (size_t)BN * DDIM;
            pBl += (size_t)BN * DDIM;
            if (++nchunk == 32) {
                nchunk = 0;
                pBh -= (size_t)E_TOTAL * DDIM;
                pBl -= (size_t)E_TOTAL * DDIM;
                pAh += (size_t)BM * DDIM;
                pAl += (size_t)BM * DDIM;
            }
        }
    };

    float bestv[4][2];
    int   besti[4][2];
    #pragma unroll
    for (int mi = 0; mi < 4; mi++)
        #pragma unroll
        for (int h = 0; h < 2; h++) { bestv[mi][h] = __int_as_float(0x7f800000); besti[mi][h] = 0; }

    float acc[4][4][4];                   // mi x ni x frag (warp tile 64x32)

    issue_load();

    uint32_t cstage = sb;                 // compute-side stage base
    int csgn = STAGE_BYTES;

    #pragma unroll 1
    for (int S = 0; S < nsteps; S++) {
        CP_WAIT0();
        __syncthreads();
        if (S + 1 < nsteps) issue_load();

        const int s8 = S & 7;
        if (s8 == 0) {
            #pragma unroll
            for (int mi = 0; mi < 4; mi++)
                #pragma unroll
                for (int ni = 0; ni < 4; ni++)
                    #pragma unroll
                    for (int q = 0; q < 4; q++) acc[mi][ni][q] = 0.0f;
        }

        const uint32_t base = cstage;
        cstage += csgn; csgn = -csgn;

        #pragma unroll
        for (int k8 = 0; k8 < 4; k8++) {
            const uint32_t ko = k8 * 32 + koff_tg;
            uint2 bh[4], bl[4];
            #pragma unroll
            for (int ni = 0; ni < 4; ni++) {
                const uint32_t rb = (uint32_t)((warpN * 32 + ni * 8 + g) * ROWB) + ko;
                bh[ni] = lds_u64(base + BH_OFF + rb);
                bl[ni] = lds_u64(base + BL_OFF + rb);
            }
            uint2 ahA[4], ahB[4], alA[4], alB[4];
            #pragma unroll
            for (int mi = 0; mi < 4; mi++) {
                const uint32_t ra = (uint32_t)((warpM * 64 + mi * 16 + g) * ROWB) + ko;
                ahA[mi] = lds_u64(base + AH_OFF + ra);
                ahB[mi] = lds_u64(base + AH_OFF + ra + 8 * ROWB);
                alA[mi] = lds_u64(base + AL_OFF + ra);
                alB[mi] = lds_u64(base + AL_OFF + ra + 8 * ROWB);
            }
            // product 1: Zh x Wh
            #pragma unroll
            for (int mi = 0; mi < 4; mi++)
                #pragma unroll
                for (int ni = 0; ni < 4; ni++)
                    mma_tf32(acc[mi][ni][0], acc[mi][ni][1], acc[mi][ni][2], acc[mi][ni][3],
                             ahA[mi].x, ahB[mi].x, ahA[mi].y, ahB[mi].y, bh[ni].x, bh[ni].y);
            // product 2: Zl x Wh
            #pragma unroll
            for (int mi = 0; mi < 4; mi++)
                #pragma unroll
                for (int ni = 0; ni < 4; ni++)
                    mma_tf32(acc[mi][ni][0], acc[mi][ni][1], acc[mi][ni][2], acc[mi][ni][3],
                             alA[mi].x, alB[mi].x, alA[mi].y, alB[mi].y, bh[ni].x, bh[ni].y);
            // product 3: Zh x Wl
            #pragma unroll
            for (int mi = 0; mi < 4; mi++)
                #pragma unroll
                for (int ni = 0; ni < 4; ni++)
                    mma_tf32(acc[mi][ni][0], acc[mi][ni][1], acc[mi][ni][2], acc[mi][ni][3],
                             ahA[mi].x, ahB[mi].x, ahA[mi].y, ahB[mi].y, bl[ni].x, bl[ni].y);
        }

        if (s8 == 7) {
            const int item = itlo + (S >> 3);
            const int e0 = (item & 31) * BN;
            #pragma unroll
            for (int ni = 0; ni < 4; ni++) {
                const int cl = warpN * 32 + ni * 8 + tg * 2;
                const float2 wq = *(const float2*)&g_wsq[e0 + cl];
                #pragma unroll
                for (int mi = 0; mi < 4; mi++) {
                    #pragma unroll
                    for (int h = 0; h < 2; h++) {
                        float d0 = wq.x - 2.0f * acc[mi][ni][h * 2 + 0];
                        float d1 = wq.y - 2.0f * acc[mi][ni][h * 2 + 1];
                        if (d0 < bestv[mi][h]) { bestv[mi][h] = d0; besti[mi][h] = e0 + cl; }
                        if (d1 < bestv[mi][h]) { bestv[mi][h] = d1; besti[mi][h] = e0 + cl + 1; }
                    }
                }
            }
            const bool last = (S + 1 == nsteps) ||
                              ((itlo + ((S + 1) >> 3)) >> 5) != (item >> 5);
            if (last) {
                const int p0 = (item >> 5) * BM;
                const int c = warpN * 4 + tg;      // 0..31
                #pragma unroll
                for (int mi = 0; mi < 4; mi++)
                    #pragma unroll
                    for (int h = 0; h < 2; h++) {
                        int p = p0 + warpM * 64 + mi * 16 + h * 8 + g;
                        g_pv[slot][p][c] = bestv[mi][h];
                        g_pi[slot][p][c] = besti[mi][h];
                        bestv[mi][h] = __int_as_float(0x7f800000);
                        besti[mi][h] = 0;
                    }
            }
        }
    }
}

// ---------------- Stage C: combine partials, gather z_q, loss partials ----------
__global__ void vq_gather(const float* __restrict__ w, float* __restrict__ out) {
    __shared__ float lsum[256];
    const int t = threadIdx.x;
    const int p = blockIdx.x * 32 + (t >> 3);
    const int j = t & 7;

    // reduce 128 (slot, col) candidates: 16 per thread, then shfl over 8 threads
    float bv = __int_as_float(0x7f800000);
    int bi = 0;
    #pragma unroll
    for (int q = 0; q < 16; q++) {
        int f = j * 16 + q;
        float v = g_pv[f >> 5][p][f & 31];
        int   i = g_pi[f >> 5][p][f & 31];
        if (v < bv || (v == bv && i < bi)) { bv = v; bi = i; }
    }
    #pragma unroll
    for (int off = 4; off >= 1; off >>= 1) {
        float ov = __shfl_down_sync(0xffffffffu, bv, off, 8);
        int   oi = __shfl_down_sync(0xffffffffu, bi, off, 8);
        if (ov < bv || (ov == bv && oi < bi)) { bv = ov; bi = oi; }
    }
    bi = __shfl_sync(0xffffffffu, bi, (t & 31) & ~7);

    const int n = p >> 12;
    const int thw = p & 4095;
    const int obase = n * 1048576 + thw;

    float acc = 0.0f;
    #pragma unroll
    for (int q = 0; q < 8; q++) {
        const int d = j * 32 + q * 4;
        float4 wv = *(const float4*)&w[(size_t)bi * DDIM + d];
        float4 zv = *(const float4*)&g_zl[(size_t)p * DDIM + d];
        out[obase + (d + 0) * 4096] = wv.x;
        out[obase + (d + 1) * 4096] = wv.y;
        out[obase + (d + 2) * 4096] = wv.z;
        out[obase + (d + 3) * 4096] = wv.w;
        float dx = wv.x - zv.x, dy = wv.y - zv.y;
        float dz = wv.z - zv.z, dw = wv.w - zv.w;
        acc += dx*dx + dy*dy + dz*dz + dw*dw;
    }
    if (j == 0) out[IDX_OFF + p] = (float)bi;

    lsum[t] = acc;
    __syncthreads();
    #pragma unroll
    for (int s = 128; s > 0; s >>= 1) {
        if (t < s) lsum[t] += lsum[t + s];
        __syncthreads();
    }
    if (t == 0) g_blockloss[blockIdx.x] = lsum[0];
}

// ---------------- Stage D: deterministic loss reduction ----------------
__global__ void vq_loss(float* __restrict__ out) {
    __shared__ float s[256];
    const int t = threadIdx.x;
    s[t] = g_blockloss[t];
    __syncthreads();
    #pragma unroll
    for (int k = 128; k > 0; k >>= 1) {
        if (t < k) s[t] += s[t + k];
        __syncthreads();
    }
    if (t == 0) out[LOSS_OFF] = 1.25f * s[0] / (float)ZQ_ELEMS;
}

// ---------------- launch ----------------
extern "C" void kernel_launch(void* const* d_in, const int* in_sizes, int n_in,
                              void* d_out, int out_size) {
    const float* z = (const float*)d_in[0];
    const float* w = (const float*)d_in[1];
    float* out = (float*)d_out;

    cudaFuncSetAttribute(vq_mma, cudaFuncAttributeMaxDynamicSharedMemorySize, SMEM_TOTAL);

    vq_prep_z<<<8192, 256>>>(z);
    vq_prep_w<<<8192, 256>>>(w);
    vq_wsq<<<1024, 256>>>(w);
    vq_mma<<<NCTA, NTHREADS, SMEM_TOTAL>>>();
    vq_gather<<<P_TOTAL / 32, 256>>>(w, out);
    vq_loss<<<1, 256>>>(out);
}

// round 9
// speedup vs baseline: 1.0229x; 1.0229x over previous
#include <cuda_runtime.h>
#include <cstdint>

// ---------------- problem constants ----------------
#define P_TOTAL 8192
#define DDIM    256
#define E_TOTAL 8192
#define NITEMS  2048                   // 64 ptiles * 32 chunks
#define NCTA    148
#define NSLOT   4

#define ZQ_ELEMS 2097152
#define LOSS_OFF 2097152
#define IDX_OFF  2097153

// ---------------- GEMM tiling ----------------
#define BM 128
#define BN 256
#define BK 32
#define NTHREADS 512
#define TS 36
#define ROWB (TS * 4)                  // 144 B per smem row
#define A_BYTES (BM * ROWB)            // 18432
#define B_BYTES (BN * ROWB)            // 36864
#define AH_OFF 0
#define AL_OFF A_BYTES
#define BH_OFF (2 * A_BYTES)
#define BL_OFF (2 * A_BYTES + B_BYTES)
#define STAGE_BYTES (2 * A_BYTES + 2 * B_BYTES)   // 110592
#define SMEM_TOTAL (2 * STAGE_BYTES)              // 221184

// ---------------- scratch ----------------
__device__ __align__(256) float g_zhi[P_TOTAL * DDIM];   // k-permuted
__device__ __align__(256) float g_zlo[P_TOTAL * DDIM];   // k-permuted
__device__ __align__(256) float g_zl [P_TOTAL * DDIM];   // plain [p][d]
__device__ __align__(256) float g_whi[E_TOTAL * DDIM];   // k-permuted
__device__ __align__(256) float g_wlo[E_TOTAL * DDIM];   // k-permuted
__device__ __align__(256) float g_wsq[E_TOTAL];
__device__ float g_pv[NSLOT][P_TOTAL][32];
__device__ int   g_pi[NSLOT][P_TOTAL][32];
__device__ float g_blockloss[256];

// ---------------- helpers ----------------
__device__ __forceinline__ uint32_t smem_u32(const void* p) {
    uint32_t a;
    asm("{ .reg .u64 t; cvta.to.shared.u64 t, %1; cvt.u32.u64 %0, t; }" : "=r"(a) : "l"(p));
    return a;
}
#define CP16(sa, ga) \
    asm volatile("cp.async.cg.shared.global [%0], [%1], 16;" :: "r"((uint32_t)(sa)), "l"(ga))
#define CP_COMMIT() asm volatile("cp.async.commit_group;" ::: "memory")
#define CP_WAIT0()  asm volatile("cp.async.wait_group 0;" ::: "memory")

__device__ __forceinline__ float tf32r(float x) {
    uint32_t r;
    asm("cvt.rna.tf32.f32 %0, %1;" : "=r"(r) : "f"(x));
    return __uint_as_float(r);
}
__device__ __forceinline__ uint2 lds_u64(uint32_t addr) {
    uint2 v;
    asm volatile("ld.shared.v2.b32 {%0,%1}, [%2];" : "=r"(v.x), "=r"(v.y) : "r"(addr));
    return v;
}
__device__ __forceinline__ void mma_tf32(float& c0, float& c1, float& c2, float& c3,
                                         uint32_t a0, uint32_t a1, uint32_t a2, uint32_t a3,
                                         uint32_t b0, uint32_t b1) {
    asm volatile("mma.sync.aligned.m16n8k8.row.col.f32.tf32.tf32.f32 "
                 "{%0,%1,%2,%3}, {%4,%5,%6,%7}, {%8,%9}, {%0,%1,%2,%3};"
                 : "+f"(c0), "+f"(c1), "+f"(c2), "+f"(c3)
                 : "r"(a0), "r"(a1), "r"(a2), "r"(a3), "r"(b0), "r"(b1));
}
// conflict-free k-permutation within each 32-float block:
// logical kk -> (b=kk>>3, tg=kk&3, c=(kk>>2)&1)
// stored word pos = (tg&1)*2 + (tg>>1)*16 + b*4 + c   (bijective on 0..31)
// bank(start) = 4g + (tg&1)*2 + (tg>>1)*16 + 4b : distinct within each half-warp
__device__ __forceinline__ int dperm(int d) {
    int blk = d & ~31;
    int kk = d & 31;
    int b = kk >> 3;
    int tg = kk & 3;
    int c = (kk >> 2) & 1;
    return blk + (tg & 1) * 2 + ((tg >> 1) << 4) + (b << 2) + c;
}

// ---------------- Stage A1: z -> (z_hi, z_lo) permuted + plain + partial init ----
__global__ void vq_prep_z(const float* __restrict__ z) {
    int idx = blockIdx.x * 256 + threadIdx.x;
    float v = z[idx];
    int n = idx >> 20, rem = idx & 1048575;
    int d = rem >> 12, thw = rem & 4095;
    int p = (n << 12) + thw;
    float hi = tf32r(v);
    int op = p * DDIM + dperm(d);
    g_zhi[op] = hi;
    g_zlo[op] = tf32r(v - hi);
    g_zl[p * DDIM + d] = v;
    if (idx < NSLOT * P_TOTAL * 32) {
        ((float*)g_pv)[idx] = __int_as_float(0x7f800000);
        ((int*)g_pi)[idx] = 0;
    }
}

// ---------------- Stage A2: w -> (w_hi, w_lo) permuted ----------------
__global__ void vq_prep_w(const float* __restrict__ w) {
    int idx = blockIdx.x * 256 + threadIdx.x;
    float v = w[idx];
    int e = idx >> 8, d = idx & 255;
    float hi = tf32r(v);
    int op = e * DDIM + dperm(d);
    g_whi[op] = hi;
    g_wlo[op] = tf32r(v - hi);
}

// ---------------- Stage A3: ||w_e||^2 ----------------
__global__ void vq_wsq(const float* __restrict__ w) {
    int gwarp = (blockIdx.x * blockDim.x + threadIdx.x) >> 5;
    int lane = threadIdx.x & 31;
    const float* row = w + (size_t)gwarp * DDIM;
    float4 a = *(const float4*)&row[lane * 4];
    float4 b = *(const float4*)&row[128 + lane * 4];
    float s = a.x*a.x + a.y*a.y + a.z*a.z + a.w*a.w
            + b.x*b.x + b.y*b.y + b.z*b.z + b.w*b.w;
    #pragma unroll
    for (int off = 16; off >= 1; off >>= 1)
        s += __shfl_down_sync(0xffffffffu, s, off);
    if (lane == 0) g_wsq[gwarp] = s;
}

// ---------------- Stage B: persistent fused 3xTF32 distance GEMM + argmin ------
__global__ __launch_bounds__(NTHREADS, 1)
void vq_mma() {
    extern __shared__ float sm[];
    const uint32_t sb = smem_u32(sm);

    const int t = threadIdx.x;
    const int lane = t & 31, wid = t >> 5;
    const int warpM = wid >> 3;          // 0..1
    const int warpN = wid & 7;           // 0..7
    const int g = lane >> 2;             // 0..7
    const int tg = lane & 3;             // 0..3
    const int bid = blockIdx.x;
    const int slot = bid & 3;
    // byte offset of this lane's k-pair within a 128B k8-group region:
    const uint32_t koff_tg = (uint32_t)((tg & 1) * 8 + ((tg >> 1) << 6));

    // exact-tiling work ranges
    const int itlo = (bid * NITEMS) / NCTA;
    const int ithi = ((bid + 1) * NITEMS) / NCTA;
    const int nsteps = (ithi - itlo) * 8;

    // loader per-thread constants (512 threads: 64 rows x 8 quad-cols)
    const int lr0 = t >> 3;              // 0..63
    const int lqc = t & 7;               // 0..7
    const uint32_t sm_a = (uint32_t)(lr0 * ROWB + lqc * 16);
    const size_t toff = (size_t)lr0 * DDIM + lqc * 4;

    // ---- incremental loader state (prefetch cursor) ----
    const float* pAh = g_zhi + (size_t)(itlo >> 5) * BM * DDIM + toff;
    const float* pAl = g_zlo + (size_t)(itlo >> 5) * BM * DDIM + toff;
    const float* pBh = g_whi + (size_t)(itlo & 31) * BN * DDIM + toff;
    const float* pBl = g_wlo + (size_t)(itlo & 31) * BN * DDIM + toff;
    int nextk = 0;                        // float offset within row (0,32,...,224)
    int nchunk = itlo & 31;
    uint32_t lstage = sb + sm_a;          // toggles between the two stages
    int lsgn = STAGE_BYTES;               // add-toggle (XOR wrong: unaligned base)

    auto issue_load = [&]() {
        const float* ah = pAh + nextk;
        const float* al = pAl + nextk;
        const float* bh = pBh + nextk;
        const float* bl = pBl + nextk;
        const uint32_t base = lstage;
        #pragma unroll
        for (int i = 0; i < 2; i++)
            CP16(base + AH_OFF + i * 64 * ROWB, ah + (size_t)i * 64 * DDIM);
        #pragma unroll
        for (int i = 0; i < 2; i++)
            CP16(base + AL_OFF + i * 64 * ROWB, al + (size_t)i * 64 * DDIM);
        #pragma unroll
        for (int i = 0; i < 4; i++)
            CP16(base + BH_OFF + i * 64 * ROWB, bh + (size_t)i * 64 * DDIM);
        #pragma unroll
        for (int i = 0; i < 4; i++)
            CP16(base + BL_OFF + i * 64 * ROWB, bl + (size_t)i * 64 * DDIM);
        CP_COMMIT();
        // advance cursor
        lstage += lsgn; lsgn = -lsgn;
        nextk += 32;
        if (nextk == 256) {
            nextk = 0;
            pBh += (size_t)BN * DDIM;
            pBl += (size_t)BN * DDIM;
            if (++nchunk == 32) {
                nchunk = 0;
                pBh -= (size_t)E_TOTAL * DDIM;
                pBl -= (size_t)E_TOTAL * DDIM;
                pAh += (size_t)BM * DDIM;
                pAl += (size_t)BM * DDIM;
            }
        }
    };

    float bestv[4][2];
    int   besti[4][2];
    #pragma unroll
    for (int mi = 0; mi < 4; mi++)
        #pragma unroll
        for (int h = 0; h < 2; h++) { bestv[mi][h] = __int_as_float(0x7f800000); besti[mi][h] = 0; }

    float acc[4][4][4];                   // mi x ni x frag (warp tile 64x32)

    issue_load();

    uint32_t cstage = sb;                 // compute-side stage base
    int csgn = STAGE_BYTES;

    #pragma unroll 1
    for (int S = 0; S < nsteps; S++) {
        CP_WAIT0();
        __syncthreads();
        if (S + 1 < nsteps) issue_load();

        const int s8 = S & 7;
        if (s8 == 0) {
            #pragma unroll
            for (int mi = 0; mi < 4; mi++)
                #pragma unroll
                for (int ni = 0; ni < 4; ni++)
                    #pragma unroll
                    for (int q = 0; q < 4; q++) acc[mi][ni][q] = 0.0f;
        }

        const uint32_t base = cstage;
        cstage += csgn; csgn = -csgn;

        #pragma unroll
        for (int k8 = 0; k8 < 4; k8++) {
            const uint32_t ko = (uint32_t)(k8 * 16) + koff_tg;   // pair (b=k8, tg)
            uint2 bh[4], bl[4];
            #pragma unroll
            for (int ni = 0; ni < 4; ni++) {
                const uint32_t rb = (uint32_t)((warpN * 32 + ni * 8 + g) * ROWB) + ko;
                bh[ni] = lds_u64(base + BH_OFF + rb);
                bl[ni] = lds_u64(base + BL_OFF + rb);
            }
            uint2 ahA[4], ahB[4], alA[4], alB[4];
            #pragma unroll
            for (int mi = 0; mi < 4; mi++) {
                const uint32_t ra = (uint32_t)((warpM * 64 + mi * 16 + g) * ROWB) + ko;
                ahA[mi] = lds_u64(base + AH_OFF + ra);
                ahB[mi] = lds_u64(base + AH_OFF + ra + 8 * ROWB);
                alA[mi] = lds_u64(base + AL_OFF + ra);
                alB[mi] = lds_u64(base + AL_OFF + ra + 8 * ROWB);
            }
            // product 1: Zh x Wh
            #pragma unroll
            for (int mi = 0; mi < 4; mi++)
                #pragma unroll
                for (int ni = 0; ni < 4; ni++)
                    mma_tf32(acc[mi][ni][0], acc[mi][ni][1], acc[mi][ni][2], acc[mi][ni][3],
                             ahA[mi].x, ahB[mi].x, ahA[mi].y, ahB[mi].y, bh[ni].x, bh[ni].y);
            // product 2: Zl x Wh
            #pragma unroll
            for (int mi = 0; mi < 4; mi++)
                #pragma unroll
                for (int ni = 0; ni < 4; ni++)
                    mma_tf32(acc[mi][ni][0], acc[mi][ni][1], acc[mi][ni][2], acc[mi][ni][3],
                             alA[mi].x, alB[mi].x, alA[mi].y, alB[mi].y, bh[ni].x, bh[ni].y);
            // product 3: Zh x Wl
            #pragma unroll
            for (int mi = 0; mi < 4; mi++)
                #pragma unroll
                for (int ni = 0; ni < 4; ni++)
                    mma_tf32(acc[mi][ni][0], acc[mi][ni][1], acc[mi][ni][2], acc[mi][ni][3],
                             ahA[mi].x, ahB[mi].x, ahA[mi].y, ahB[mi].y, bl[ni].x, bl[ni].y);
        }

        if (s8 == 7) {
            const int item = itlo + (S >> 3);
            const int e0 = (item & 31) * BN;
            #pragma unroll
            for (int ni = 0; ni < 4; ni++) {
                const int cl = warpN * 32 + ni * 8 + tg * 2;
                const float2 wq = *(const float2*)&g_wsq[e0 + cl];
                #pragma unroll
                for (int mi = 0; mi < 4; mi++) {
                    #pragma unroll
                    for (int h = 0; h < 2; h++) {
                        float d0 = wq.x - 2.0f * acc[mi][ni][h * 2 + 0];
                        float d1 = wq.y - 2.0f * acc[mi][ni][h * 2 + 1];
                        if (d0 < bestv[mi][h]) { bestv[mi][h] = d0; besti[mi][h] = e0 + cl; }
                        if (d1 < bestv[mi][h]) { bestv[mi][h] = d1; besti[mi][h] = e0 + cl + 1; }
                    }
                }
            }
            const bool last = (S + 1 == nsteps) ||
                              ((itlo + ((S + 1) >> 3)) >> 5) != (item >> 5);
            if (last) {
                const int p0 = (item >> 5) * BM;
                const int c = warpN * 4 + tg;      // 0..31
                #pragma unroll
                for (int mi = 0; mi < 4; mi++)
                    #pragma unroll
                    for (int h = 0; h < 2; h++) {
                        int p = p0 + warpM * 64 + mi * 16 + h * 8 + g;
                        g_pv[slot][p][c] = bestv[mi][h];
                        g_pi[slot][p][c] = besti[mi][h];
                        bestv[mi][h] = __int_as_float(0x7f800000);
                        besti[mi][h] = 0;
                    }
            }
        }
    }
}

// ---------------- Stage C: combine partials, gather z_q, loss partials ----------
__global__ void vq_gather(const float* __restrict__ w, float* __restrict__ out) {
    __shared__ float lsum[256];
    const int t = threadIdx.x;
    const int p = blockIdx.x * 32 + (t >> 3);
    const int j = t & 7;

    // reduce 128 (slot, col) candidates: 16 per thread, then shfl over 8 threads
    float bv = __int_as_float(0x7f800000);
    int bi = 0;
    #pragma unroll
    for (int q = 0; q < 16; q++) {
        int f = j * 16 + q;
        float v = g_pv[f >> 5][p][f & 31];
        int   i = g_pi[f >> 5][p][f & 31];
        if (v < bv || (v == bv && i < bi)) { bv = v; bi = i; }
    }
    #pragma unroll
    for (int off = 4; off >= 1; off >>= 1) {
        float ov = __shfl_down_sync(0xffffffffu, bv, off, 8);
        int   oi = __shfl_down_sync(0xffffffffu, bi, off, 8);
        if (ov < bv || (ov == bv && oi < bi)) { bv = ov; bi = oi; }
    }
    bi = __shfl_sync(0xffffffffu, bi, (t & 31) & ~7);

    const int n = p >> 12;
    const int thw = p & 4095;
    const int obase = n * 1048576 + thw;

    float acc = 0.0f;
    #pragma unroll
    for (int q = 0; q < 8; q++) {
        const int d = j * 32 + q * 4;
        float4 wv = *(const float4*)&w[(size_t)bi * DDIM + d];
        float4 zv = *(const float4*)&g_zl[(size_t)p * DDIM + d];
        out[obase + (d + 0) * 4096] = wv.x;
        out[obase + (d + 1) * 4096] = wv.y;
        out[obase + (d + 2) * 4096] = wv.z;
        out[obase + (d + 3) * 4096] = wv.w;
        float dx = wv.x - zv.x, dy = wv.y - zv.y;
        float dz = wv.z - zv.z, dw = wv.w - zv.w;
        acc += dx*dx + dy*dy + dz*dz + dw*dw;
    }
    if (j == 0) out[IDX_OFF + p] = (float)bi;

    lsum[t] = acc;
    __syncthreads();
    #pragma unroll
    for (int s = 128; s > 0; s >>= 1) {
        if (t < s) lsum[t] += lsum[t + s];
        __syncthreads();
    }
    if (t == 0) g_blockloss[blockIdx.x] = lsum[0];
}

// ---------------- Stage D: deterministic loss reduction ----------------
__global__ void vq_loss(float* __restrict__ out) {
    __shared__ float s[256];
    const int t = threadIdx.x;
    s[t] = g_blockloss[t];
    __syncthreads();
    #pragma unroll
    for (int k = 128; k > 0; k >>= 1) {
        if (t < k) s[t] += s[t + k];
        __syncthreads();
    }
    if (t == 0) out[LOSS_OFF] = 1.25f * s[0] / (float)ZQ_ELEMS;
}

// ---------------- launch ----------------
extern "C" void kernel_launch(void* const* d_in, const int* in_sizes, int n_in,
                              void* d_out, int out_size) {
    const float* z = (const float*)d_in[0];
    const float* w = (const float*)d_in[1];
    float* out = (float*)d_out;

    cudaFuncSetAttribute(vq_mma, cudaFuncAttributeMaxDynamicSharedMemorySize, SMEM_TOTAL);

    vq_prep_z<<<8192, 256>>>(z);
    vq_prep_w<<<8192, 256>>>(w);
    vq_wsq<<<1024, 256>>>(w);
    vq_mma<<<NCTA, NTHREADS, SMEM_TOTAL>>>();
    vq_gather<<<P_TOTAL / 32, 256>>>(w, out);
    vq_loss<<<1, 256>>>(out);
}

// round 10
// speedup vs baseline: 1.2468x; 1.2189x over previous
#include <cuda_runtime.h>
#include <cuda_bf16.h>
#include <cstdint>

// ---------------- problem constants ----------------
#define P_TOTAL 8192
#define DDIM    256
#define E_TOTAL 8192
#define NITEMS  2048                   // 64 ptiles * 32 chunks
#define NCTA    148
#define NSLOT   4

#define ZQ_ELEMS 2097152
#define LOSS_OFF 2097152
#define IDX_OFF  2097153

// ---------------- GEMM tiling ----------------
#define BM 128
#define BN 256
#define BK 32
#define NTHREADS 512
#define TS 36
#define ROWB (TS * 4)                  // 144 B per tf32 smem row
// stage layout (bytes)
#define AH_OFF  0                      // tf32 Zh: 128 x 144      = 18432
#define BH_OFF  18432                  // tf32 Wh: 256 x 144      = 36864
#define ABH_OFF 55296                  // bf16 Zh: 2 x 128 x 32   = 8192
#define ABL_OFF 63488                  // bf16 Zl: 8192
#define BBH_OFF 71680                  // bf16 Wh: 2 x 256 x 32   = 16384
#define BBL_OFF 88064                  // bf16 Wl: 16384
#define STAGE_BYTES 104448
#define SMEM_TOTAL (2 * STAGE_BYTES)   // 208896

// ---------------- scratch ----------------
__device__ __align__(256) float    g_zhi[P_TOTAL * DDIM];    // tf32, k-permuted
__device__ __align__(256) float    g_zl [P_TOTAL * DDIM];    // plain [p][d]
__device__ __align__(256) uint32_t g_zbh[P_TOTAL * DDIM/2];  // bf16 pairs, swizzled
__device__ __align__(256) uint32_t g_zbl[P_TOTAL * DDIM/2];
__device__ __align__(256) float    g_whi[E_TOTAL * DDIM];    // tf32, k-permuted
__device__ __align__(256) uint32_t g_wbh[E_TOTAL * DDIM/2];
__device__ __align__(256) uint32_t g_wbl[E_TOTAL * DDIM/2];
__device__ __align__(256) float    g_wsq[E_TOTAL];
__device__ float g_pv[NSLOT][P_TOTAL][32];
__device__ int   g_pi[NSLOT][P_TOTAL][32];
__device__ float g_blockloss[256];

// ---------------- helpers ----------------
__device__ __forceinline__ uint32_t smem_u32(const void* p) {
    uint32_t a;
    asm("{ .reg .u64 t; cvta.to.shared.u64 t, %1; cvt.u32.u64 %0, t; }" : "=r"(a) : "l"(p));
    return a;
}
#define CP16(sa, ga) \
    asm volatile("cp.async.cg.shared.global [%0], [%1], 16;" :: "r"((uint32_t)(sa)), "l"(ga))
#define CP_COMMIT() asm volatile("cp.async.commit_group;" ::: "memory")
#define CP_WAIT0()  asm volatile("cp.async.wait_group 0;" ::: "memory")

__device__ __forceinline__ float tf32r(float x) {
    uint32_t r;
    asm("cvt.rna.tf32.f32 %0, %1;" : "=r"(r) : "f"(x));
    return __uint_as_float(r);
}
__device__ __forceinline__ uint2 lds_u64(uint32_t addr) {
    uint2 v;
    asm volatile("ld.shared.v2.b32 {%0,%1}, [%2];" : "=r"(v.x), "=r"(v.y) : "r"(addr));
    return v;
}
__device__ __forceinline__ void mma_tf32(float& c0, float& c1, float& c2, float& c3,
                                         uint32_t a0, uint32_t a1, uint32_t a2, uint32_t a3,
                                         uint32_t b0, uint32_t b1) {
    asm volatile("mma.sync.aligned.m16n8k8.row.col.f32.tf32.tf32.f32 "
                 "{%0,%1,%2,%3}, {%4,%5,%6,%7}, {%8,%9}, {%0,%1,%2,%3};"
                 : "+f"(c0), "+f"(c1), "+f"(c2), "+f"(c3)
                 : "r"(a0), "r"(a1), "r"(a2), "r"(a3), "r"(b0), "r"(b1));
}
__device__ __forceinline__ void mma_bf16(float& c0, float& c1, float& c2, float& c3,
                                         uint32_t a0, uint32_t a1, uint32_t a2, uint32_t a3,
                                         uint32_t b0, uint32_t b1) {
    asm volatile("mma.sync.aligned.m16n8k16.row.col.f32.bf16.bf16.f32 "
                 "{%0,%1,%2,%3}, {%4,%5,%6,%7}, {%8,%9}, {%0,%1,%2,%3};"
                 : "+f"(c0), "+f"(c1), "+f"(c2), "+f"(c3)
                 : "r"(a0), "r"(a1), "r"(a2), "r"(a3), "r"(b0), "r"(b1));
}
// tf32 conflict-free permutation (validated R9)
__device__ __forceinline__ int dperm(int d) {
    int blk = d & ~31;
    int kk = d & 31;
    int b = kk >> 3;
    int tg = kk & 3;
    int c = (kk >> 2) & 1;
    return blk + (tg & 1) * 2 + ((tg >> 1) << 4) + (b << 2) + c;
}
__device__ __forceinline__ uint32_t packbf2(float lo, float hi) {
    __nv_bfloat162 v = __floats2bfloat162_rn(lo, hi);
    return *reinterpret_cast<uint32_t*>(&v);
}
// bf16 packed word index within a row (128 words): row r (use r&3), element pair d0(even)
__device__ __forceinline__ int bfwidx(int d0, int r) {
    int kb = d0 >> 4;
    int kk = d0 & 15;
    int pr = (kk >> 1) & 3;
    int c  = kk >> 3;
    return kb * 8 + ((pr ^ (r & 3)) << 1) + c;
}

// ---------------- Stage A1: z -> tf32 hi + bf16 (hi,lo) + plain + partial init --
__global__ void vq_prep_z(const float* __restrict__ z) {
    int idx = blockIdx.x * 256 + threadIdx.x;   // 0..1048575
    int n = idx >> 19;
    int rem = idx & 524287;
    int dp = rem >> 12;        // 0..127
    int thw = rem & 4095;
    int d0 = dp * 2;
    float v0 = z[((n << 8) + d0) * 4096 + thw];
    float v1 = z[((n << 8) + d0 + 1) * 4096 + thw];
    int p = (n << 12) + thw;
    float h0 = tf32r(v0), h1 = tf32r(v1);
    g_zhi[p * DDIM + dperm(d0)]     = h0;
    g_zhi[p * DDIM + dperm(d0 + 1)] = h1;
    g_zl[p * DDIM + d0]     = v0;
    g_zl[p * DDIM + d0 + 1] = v1;
    int wi = p * 128 + bfwidx(d0, p);
    g_zbh[wi] = packbf2(h0, h1);
    g_zbl[wi] = packbf2(v0 - h0, v1 - h1);
    ((float*)g_pv)[idx] = __int_as_float(0x7f800000);
    ((int*)g_pi)[idx] = 0;
}

// ---------------- Stage A2: w -> tf32 hi + bf16 (hi,lo) ----------------
__global__ void vq_prep_w(const float* __restrict__ w) {
    int idx = blockIdx.x * 256 + threadIdx.x;   // 0..1048575
    int e = idx >> 7;
    int dp = idx & 127;
    int d0 = dp * 2;
    float v0 = w[e * DDIM + d0];
    float v1 = w[e * DDIM + d0 + 1];
    float h0 = tf32r(v0), h1 = tf32r(v1);
    g_whi[e * DDIM + dperm(d0)]     = h0;
    g_whi[e * DDIM + dperm(d0 + 1)] = h1;
    int wi = e * 128 + bfwidx(d0, e);
    g_wbh[wi] = packbf2(h0, h1);
    g_wbl[wi] = packbf2(v0 - h0, v1 - h1);
}

// ---------------- Stage A3: ||w_e||^2 ----------------
__global__ void vq_wsq(const float* __restrict__ w) {
    int gwarp = (blockIdx.x * blockDim.x + threadIdx.x) >> 5;
    int lane = threadIdx.x & 31;
    const float* row = w + (size_t)gwarp * DDIM;
    float4 a = *(const float4*)&row[lane * 4];
    float4 b = *(const float4*)&row[128 + lane * 4];
    float s = a.x*a.x + a.y*a.y + a.z*a.z + a.w*a.w
            + b.x*b.x + b.y*b.y + b.z*b.z + b.w*b.w;
    #pragma unroll
    for (int off = 16; off >= 1; off >>= 1)
        s += __shfl_down_sync(0xffffffffu, s, off);
    if (lane == 0) g_wsq[gwarp] = s;
}

// ---------------- Stage B: persistent tf32+bf16 distance GEMM + argmin --------
__global__ __launch_bounds__(NTHREADS, 1)
void vq_mma() {
    extern __shared__ float sm[];
    const uint32_t sb = smem_u32(sm);

    const int t = threadIdx.x;
    const int lane = t & 31, wid = t >> 5;
    const int warpM = wid >> 3;          // 0..1
    const int warpN = wid & 7;           // 0..7
    const int g = lane >> 2;             // 0..7
    const int tg = lane & 3;             // 0..3
    const int bid = blockIdx.x;
    const int slot = bid & 3;
    const uint32_t koff_tg = (uint32_t)((tg & 1) * 8 + ((tg >> 1) << 6));
    const uint32_t xorsw = (uint32_t)((tg ^ (g & 3)) << 3);   // bf16 swizzle (bytes)

    // exact-tiling work ranges
    const int itlo = (bid * NITEMS) / NCTA;
    const int ithi = ((bid + 1) * NITEMS) / NCTA;
    const int nsteps = (ithi - itlo) * 8;

    // tf32 loader constants
    const int lr0 = t >> 3;              // 0..63
    const int lqc = t & 7;               // 0..7
    const uint32_t sm_a = (uint32_t)(lr0 * ROWB + lqc * 16);
    const size_t toff = (size_t)lr0 * DDIM + lqc * 4;
    // bf16 A loader: (bA, rA, hA)
    const int bA = t >> 8, rA = (t >> 1) & 127, hA = t & 1;
    const uint32_t dstA = (uint32_t)(bA * 4096 + rA * 32 + hA * 16);
    // bf16 B loader: block 0 at (rB, hB); block 1 = +8 words src, +8192 B dst
    const int rB = t >> 1, hB = t & 1;
    const uint32_t dstB = (uint32_t)(rB * 32 + hB * 16);

    // ---- incremental loader cursors ----
    const int pt0 = itlo >> 5, ch0 = itlo & 31;
    const float*    pAh  = g_zhi + (size_t)pt0 * BM * DDIM + toff;
    const float*    pBh  = g_whi + (size_t)ch0 * BN * DDIM + toff;
    const uint32_t* pZbh = g_zbh + (size_t)(pt0 * BM + rA) * 128 + bA * 8 + hA * 4;
    const uint32_t* pZbl = g_zbl + (size_t)(pt0 * BM + rA) * 128 + bA * 8 + hA * 4;
    const uint32_t* pWbh = g_wbh + (size_t)(ch0 * BN + rB) * 128 + hB * 4;
    const uint32_t* pWbl = g_wbl + (size_t)(ch0 * BN + rB) * 128 + hB * 4;
    int nextk = 0;                        // float offset within row
    int nchunk = ch0;
    uint32_t lstage = sb;
    int lsgn = STAGE_BYTES;

    auto issue_load = [&]() {
        const uint32_t base = lstage;
        const float* ah = pAh + nextk;
        const float* bh = pBh + nextk;
        const int kw = nextk >> 1;        // packed-word offset
        CP16(base + AH_OFF + sm_a,                ah);
        CP16(base + AH_OFF + sm_a + 64 * ROWB,    ah + (size_t)64 * DDIM);
        #pragma unroll
        for (int i = 0; i < 4; i++)
            CP16(base + BH_OFF + sm_a + i * 64 * ROWB, bh + (size_t)i * 64 * DDIM);
        CP16(base + ABH_OFF + dstA, pZbh + kw);
        CP16(base + ABL_OFF + dstA, pZbl + kw);
        CP16(base + BBH_OFF + dstB,        pWbh + kw);
        CP16(base + BBH_OFF + dstB + 8192, pWbh + kw + 8);
        CP16(base + BBL_OFF + dstB,        pWbl + kw);
        CP16(base + BBL_OFF + dstB + 8192, pWbl + kw + 8);
        CP_COMMIT();
        lstage += lsgn; lsgn = -lsgn;
        nextk += 32;
        if (nextk == 256) {
            nextk = 0;
            pBh  += (size_t)BN * DDIM;
            pWbh += (size_t)BN * 128;
            pWbl += (size_t)BN * 128;
            if (++nchunk == 32) {
                nchunk = 0;
                pBh  -= (size_t)E_TOTAL * DDIM;
                pWbh -= (size_t)E_TOTAL * 128;
                pWbl -= (size_t)E_TOTAL * 128;
                pAh  += (size_t)BM * DDIM;
                pZbh += (size_t)BM * 128;
                pZbl += (size_t)BM * 128;
            }
        }
    };

    float bestv[4][2];
    int   besti[4][2];
    #pragma unroll
    for (int mi = 0; mi < 4; mi++)
        #pragma unroll
        for (int h = 0; h < 2; h++) { bestv[mi][h] = __int_as_float(0x7f800000); besti[mi][h] = 0; }

    float acc[4][4][4];

    issue_load();

    uint32_t cstage = sb;
    int csgn = STAGE_BYTES;

    #pragma unroll 1
    for (int S = 0; S < nsteps; S++) {
        CP_WAIT0();
        __syncthreads();
        if (S + 1 < nsteps) issue_load();

        const int s8 = S & 7;
        if (s8 == 0) {
            #pragma unroll
            for (int mi = 0; mi < 4; mi++)
                #pragma unroll
                for (int ni = 0; ni < 4; ni++)
                    #pragma unroll
                    for (int q = 0; q < 4; q++) acc[mi][ni][q] = 0.0f;
        }

        const uint32_t base = cstage;
        cstage += csgn; csgn = -csgn;

        #pragma unroll
        for (int b = 0; b < 2; b++) {
            // ---- main product: Zh x Wh (tf32, k8 = 2b, 2b+1) ----
            #pragma unroll
            for (int kh = 0; kh < 2; kh++) {
                const uint32_t ko = (uint32_t)((2 * b + kh) * 16) + koff_tg;
                uint2 bh[4];
                #pragma unroll
                for (int ni = 0; ni < 4; ni++)
                    bh[ni] = lds_u64(base + BH_OFF +
                                     (uint32_t)((warpN * 32 + ni * 8 + g) * ROWB) + ko);
                #pragma unroll
                for (int mi = 0; mi < 4; mi++) {
                    const uint32_t ra = (uint32_t)((warpM * 64 + mi * 16 + g) * ROWB) + ko;
                    uint2 aA = lds_u64(base + AH_OFF + ra);
                    uint2 aB = lds_u64(base + AH_OFF + ra + 8 * ROWB);
                    #pragma unroll
                    for (int ni = 0; ni < 4; ni++)
                        mma_tf32(acc[mi][ni][0], acc[mi][ni][1], acc[mi][ni][2], acc[mi][ni][3],
                                 aA.x, aB.x, aA.y, aB.y, bh[ni].x, bh[ni].y);
                }
            }
            // ---- corrections (bf16 m16n8k16, k16-block b) ----
            const uint32_t aboff = (uint32_t)(b * 4096);
            const uint32_t bboff = (uint32_t)(b * 8192);
            // corr1: Zl x Wh
            {
                uint2 wb[4];
                #pragma unroll
                for (int ni = 0; ni < 4; ni++)
                    wb[ni] = lds_u64(base + BBH_OFF + bboff +
                                     (uint32_t)((warpN * 32 + ni * 8 + g) * 32) + xorsw);
                #pragma unroll
                for (int mi = 0; mi < 4; mi++) {
                    const uint32_t ra = aboff +
                        (uint32_t)((warpM * 64 + mi * 16 + g) * 32) + xorsw;
                    uint2 vA = lds_u64(base + ABL_OFF + ra);
                    uint2 vB = lds_u64(base + ABL_OFF + ra + 256);
                    #pragma unroll
                    for (int ni = 0; ni < 4; ni++)
                        mma_bf16(acc[mi][ni][0], acc[mi][ni][1], acc[mi][ni][2], acc[mi][ni][3],
                                 vA.x, vB.x, vA.y, vB.y, wb[ni].x, wb[ni].y);
                }
            }
            // corr2: Zh x Wl
            {
                uint2 wb[4];
                #pragma unroll
                for (int ni = 0; ni < 4; ni++)
                    wb[ni] = lds_u64(base + BBL_OFF + bboff +
                                     (uint32_t)((warpN * 32 + ni * 8 + g) * 32) + xorsw);
                #pragma unroll
                for (int mi = 0; mi < 4; mi++) {
                    const uint32_t ra = aboff +
                        (uint32_t)((warpM * 64 + mi * 16 + g) * 32) + xorsw;
                    uint2 vA = lds_u64(base + ABH_OFF + ra);
                    uint2 vB = lds_u64(base + ABH_OFF + ra + 256);
                    #pragma unroll
                    for (int ni = 0; ni < 4; ni++)
                        mma_bf16(acc[mi][ni][0], acc[mi][ni][1], acc[mi][ni][2], acc[mi][ni][3],
                                 vA.x, vB.x, vA.y, vB.y, wb[ni].x, wb[ni].y);
                }
            }
        }

        if (s8 == 7) {
            const int item = itlo + (S >> 3);
            const int e0 = (item & 31) * BN;
            #pragma unroll
            for (int ni = 0; ni < 4; ni++) {
                const int cl = warpN * 32 + ni * 8 + tg * 2;
                const float2 wq = *(const float2*)&g_wsq[e0 + cl];
                #pragma unroll
                for (int mi = 0; mi < 4; mi++) {
                    #pragma unroll
                    for (int h = 0; h < 2; h++) {
                        float d0 = wq.x - 2.0f * acc[mi][ni][h * 2 + 0];
                        float d1 = wq.y - 2.0f * acc[mi][ni][h * 2 + 1];
                        if (d0 < bestv[mi][h]) { bestv[mi][h] = d0; besti[mi][h] = e0 + cl; }
                        if (d1 < bestv[mi][h]) { bestv[mi][h] = d1; besti[mi][h] = e0 + cl + 1; }
                    }
                }
            }
            const bool last = (S + 1 == nsteps) ||
                              ((itlo + ((S + 1) >> 3)) >> 5) != (item >> 5);
            if (last) {
                const int p0 = (item >> 5) * BM;
                const int c = warpN * 4 + tg;
                #pragma unroll
                for (int mi = 0; mi < 4; mi++)
                    #pragma unroll
                    for (int h = 0; h < 2; h++) {
                        int p = p0 + warpM * 64 + mi * 16 + h * 8 + g;
                        g_pv[slot][p][c] = bestv[mi][h];
                        g_pi[slot][p][c] = besti[mi][h];
                        bestv[mi][h] = __int_as_float(0x7f800000);
                        besti[mi][h] = 0;
                    }
            }
        }
    }
}

// ---------------- Stage C: combine partials, gather z_q, loss partials ----------
__global__ void vq_gather(const float* __restrict__ w, float* __restrict__ out) {
    __shared__ float lsum[256];
    const int t = threadIdx.x;
    const int p = blockIdx.x * 32 + (t >> 3);
    const int j = t & 7;

    float bv = __int_as_float(0x7f800000);
    int bi = 0;
    #pragma unroll
    for (int q = 0; q < 16; q++) {
        int f = j * 16 + q;
        float v = g_pv[f >> 5][p][f & 31];
        int   i = g_pi[f >> 5][p][f & 31];
        if (v < bv || (v == bv && i < bi)) { bv = v; bi = i; }
    }
    #pragma unroll
    for (int off = 4; off >= 1; off >>= 1) {
        float ov = __shfl_down_sync(0xffffffffu, bv, off, 8);
        int   oi = __shfl_down_sync(0xffffffffu, bi, off, 8);
        if (ov < bv || (ov == bv && oi < bi)) { bv = ov; bi = oi; }
    }
    bi = __shfl_sync(0xffffffffu, bi, (t & 31) & ~7);

    const int n = p >> 12;
    const int thw = p & 4095;
    const int obase = n * 1048576 + thw;

    float acc = 0.0f;
    #pragma unroll
    for (int q = 0; q < 8; q++) {
        const int d = j * 32 + q * 4;
        float4 wv = *(const float4*)&w[(size_t)bi * DDIM + d];
        float4 zv = *(const float4*)&g_zl[(size_t)p * DDIM + d];
        out[obase + (d + 0) * 4096] = wv.x;
        out[obase + (d + 1) * 4096] = wv.y;
        out[obase + (d + 2) * 4096] = wv.z;
        out[obase + (d + 3) * 4096] = wv.w;
        float dx = wv.x - zv.x, dy = wv.y - zv.y;
        float dz = wv.z - zv.z, dw = wv.w - zv.w;
        acc += dx*dx + dy*dy + dz*dz + dw*dw;
    }
    if (j == 0) out[IDX_OFF + p] = (float)bi;

    lsum[t] = acc;
    __syncthreads();
    #pragma unroll
    for (int s = 128; s > 0; s >>= 1) {
        if (t < s) lsum[t] += lsum[t + s];
        __syncthreads();
    }
    if (t == 0) g_blockloss[blockIdx.x] = lsum[0];
}

// ---------------- Stage D: deterministic loss reduction ----------------
__global__ void vq_loss(float* __restrict__ out) {
    __shared__ float s[256];
    const int t = threadIdx.x;
    s[t] = g_blockloss[t];
    __syncthreads();
    #pragma unroll
    for (int k = 128; k > 0; k >>= 1) {
        if (t < k) s[t] += s[t + k];
        __syncthreads();
    }
    if (t == 0) out[LOSS_OFF] = 1.25f * s[0] / (float)ZQ_ELEMS;
}

// ---------------- launch ----------------
extern "C" void kernel_launch(void* const* d_in, const int* in_sizes, int n_in,
                              void* d_out, int out_size) {
    const float* z = (const float*)d_in[0];
    const float* w = (const float*)d_in[1];
    float* out = (float*)d_out;

    cudaFuncSetAttribute(vq_mma, cudaFuncAttributeMaxDynamicSharedMemorySize, SMEM_TOTAL);

    vq_prep_z<<<4096, 256>>>(z);
    vq_prep_w<<<4096, 256>>>(w);
    vq_wsq<<<1024, 256>>>(w);
    vq_mma<<<NCTA, NTHREADS, SMEM_TOTAL>>>();
    vq_gather<<<P_TOTAL / 32, 256>>>(w, out);
    vq_loss<<<1, 256>>>(out);
}

// round 11
// speedup vs baseline: 1.3097x; 1.0504x over previous
#include <cuda_runtime.h>
#include <cuda_bf16.h>
#include <cstdint>

// ---------------- problem constants ----------------
#define P_TOTAL 8192
#define DDIM    256
#define E_TOTAL 8192
#define NITEMS  2048                   // 64 ptiles * 32 chunks
#define NCTA    148
#define NSLOT   4

#define ZQ_ELEMS 2097152
#define LOSS_OFF 2097152
#define IDX_OFF  2097153

// ---------------- GEMM tiling ----------------
#define BM 128
#define BN 256
#define BK 32
#define NTHREADS 256
#define TS 36
#define ROWB (TS * 4)                  // 144 B per tf32 smem row
// stage layout (bytes)
#define AH_OFF  0                      // tf32 Zh: 128 x 144      = 18432
#define BH_OFF  18432                  // tf32 Wh: 256 x 144      = 36864
#define ABH_OFF 55296                  // bf16 Zh: 2 x 128 x 32   = 8192
#define ABL_OFF 63488                  // bf16 Zl: 8192
#define BBH_OFF 71680                  // bf16 Wh: 2 x 256 x 32   = 16384
#define BBL_OFF 88064                  // bf16 Wl: 16384
#define STAGE_BYTES 104448
#define SMEM_TOTAL (2 * STAGE_BYTES)   // 208896

// ---------------- scratch ----------------
__device__ __align__(256) float    g_zhi[P_TOTAL * DDIM];    // tf32, k-permuted
__device__ __align__(256) float    g_zl [P_TOTAL * DDIM];    // plain [p][d]
__device__ __align__(256) uint32_t g_zbh[P_TOTAL * DDIM/2];  // bf16 pairs, swizzled
__device__ __align__(256) uint32_t g_zbl[P_TOTAL * DDIM/2];
__device__ __align__(256) float    g_whi[E_TOTAL * DDIM];    // tf32, k-permuted
__device__ __align__(256) uint32_t g_wbh[E_TOTAL * DDIM/2];
__device__ __align__(256) uint32_t g_wbl[E_TOTAL * DDIM/2];
__device__ __align__(256) float    g_wsq[E_TOTAL];
__device__ float g_pv[NSLOT][P_TOTAL][16];
__device__ int   g_pi[NSLOT][P_TOTAL][16];
__device__ float g_blockloss[256];

// ---------------- helpers ----------------
__device__ __forceinline__ uint32_t smem_u32(const void* p) {
    uint32_t a;
    asm("{ .reg .u64 t; cvta.to.shared.u64 t, %1; cvt.u32.u64 %0, t; }" : "=r"(a) : "l"(p));
    return a;
}
#define CP16(sa, ga) \
    asm volatile("cp.async.cg.shared.global [%0], [%1], 16;" :: "r"((uint32_t)(sa)), "l"(ga))
#define CP_COMMIT() asm volatile("cp.async.commit_group;" ::: "memory")
#define CP_WAIT0()  asm volatile("cp.async.wait_group 0;" ::: "memory")

__device__ __forceinline__ float tf32r(float x) {
    uint32_t r;
    asm("cvt.rna.tf32.f32 %0, %1;" : "=r"(r) : "f"(x));
    return __uint_as_float(r);
}
__device__ __forceinline__ uint2 lds_u64(uint32_t addr) {
    uint2 v;
    asm volatile("ld.shared.v2.b32 {%0,%1}, [%2];" : "=r"(v.x), "=r"(v.y) : "r"(addr));
    return v;
}
__device__ __forceinline__ void mma_tf32(float& c0, float& c1, float& c2, float& c3,
                                         uint32_t a0, uint32_t a1, uint32_t a2, uint32_t a3,
                                         uint32_t b0, uint32_t b1) {
    asm volatile("mma.sync.aligned.m16n8k8.row.col.f32.tf32.tf32.f32 "
                 "{%0,%1,%2,%3}, {%4,%5,%6,%7}, {%8,%9}, {%0,%1,%2,%3};"
                 : "+f"(c0), "+f"(c1), "+f"(c2), "+f"(c3)
                 : "r"(a0), "r"(a1), "r"(a2), "r"(a3), "r"(b0), "r"(b1));
}
__device__ __forceinline__ void mma_bf16(float& c0, float& c1, float& c2, float& c3,
                                         uint32_t a0, uint32_t a1, uint32_t a2, uint32_t a3,
                                         uint32_t b0, uint32_t b1) {
    asm volatile("mma.sync.aligned.m16n8k16.row.col.f32.bf16.bf16.f32 "
                 "{%0,%1,%2,%3}, {%4,%5,%6,%7}, {%8,%9}, {%0,%1,%2,%3};"
                 : "+f"(c0), "+f"(c1), "+f"(c2), "+f"(c3)
                 : "r"(a0), "r"(a1), "r"(a2), "r"(a3), "r"(b0), "r"(b1));
}
// tf32 conflict-free permutation (validated R9)
__device__ __forceinline__ int dperm(int d) {
    int blk = d & ~31;
    int kk = d & 31;
    int b = kk >> 3;
    int tg = kk & 3;
    int c = (kk >> 2) & 1;
    return blk + (tg & 1) * 2 + ((tg >> 1) << 4) + (b << 2) + c;
}
__device__ __forceinline__ uint32_t packbf2(float lo, float hi) {
    __nv_bfloat162 v = __floats2bfloat162_rn(lo, hi);
    return *reinterpret_cast<uint32_t*>(&v);
}
// bf16 packed word index within a row (128 words): row r (use r&3), element pair d0(even)
__device__ __forceinline__ int bfwidx(int d0, int r) {
    int kb = d0 >> 4;
    int kk = d0 & 15;
    int pr = (kk >> 1) & 3;
    int c  = kk >> 3;
    return kb * 8 + ((pr ^ (r & 3)) << 1) + c;
}

// ---------------- Stage A1: z -> tf32 hi + bf16 (hi,lo) + plain + partial init --
__global__ void vq_prep_z(const float* __restrict__ z) {
    int idx = blockIdx.x * 256 + threadIdx.x;   // 0..1048575
    int n = idx >> 19;
    int rem = idx & 524287;
    int dp = rem >> 12;        // 0..127
    int thw = rem & 4095;
    int d0 = dp * 2;
    float v0 = z[((n << 8) + d0) * 4096 + thw];
    float v1 = z[((n << 8) + d0 + 1) * 4096 + thw];
    int p = (n << 12) + thw;
    float h0 = tf32r(v0), h1 = tf32r(v1);
    g_zhi[p * DDIM + dperm(d0)]     = h0;
    g_zhi[p * DDIM + dperm(d0 + 1)] = h1;
    g_zl[p * DDIM + d0]     = v0;
    g_zl[p * DDIM + d0 + 1] = v1;
    int wi = p * 128 + bfwidx(d0, p);
    g_zbh[wi] = packbf2(h0, h1);
    g_zbl[wi] = packbf2(v0 - h0, v1 - h1);
    if (idx < NSLOT * P_TOTAL * 16) {
        ((float*)g_pv)[idx] = __int_as_float(0x7f800000);
        ((int*)g_pi)[idx] = 0;
    }
}

// ---------------- Stage A2: w -> tf32 hi + bf16 (hi,lo) ----------------
__global__ void vq_prep_w(const float* __restrict__ w) {
    int idx = blockIdx.x * 256 + threadIdx.x;   // 0..1048575
    int e = idx >> 7;
    int dp = idx & 127;
    int d0 = dp * 2;
    float v0 = w[e * DDIM + d0];
    float v1 = w[e * DDIM + d0 + 1];
    float h0 = tf32r(v0), h1 = tf32r(v1);
    g_whi[e * DDIM + dperm(d0)]     = h0;
    g_whi[e * DDIM + dperm(d0 + 1)] = h1;
    int wi = e * 128 + bfwidx(d0, e);
    g_wbh[wi] = packbf2(h0, h1);
    g_wbl[wi] = packbf2(v0 - h0, v1 - h1);
}

// ---------------- Stage A3: ||w_e||^2 ----------------
__global__ void vq_wsq(const float* __restrict__ w) {
    int gwarp = (blockIdx.x * blockDim.x + threadIdx.x) >> 5;
    int lane = threadIdx.x & 31;
    const float* row = w + (size_t)gwarp * DDIM;
    float4 a = *(const float4*)&row[lane * 4];
    float4 b = *(const float4*)&row[128 + lane * 4];
    float s = a.x*a.x + a.y*a.y + a.z*a.z + a.w*a.w
            + b.x*b.x + b.y*b.y + b.z*b.z + b.w*b.w;
    #pragma unroll
    for (int off = 16; off >= 1; off >>= 1)
        s += __shfl_down_sync(0xffffffffu, s, off);
    if (lane == 0) g_wsq[gwarp] = s;
}

// ---------------- Stage B: persistent tf32+bf16 distance GEMM + argmin --------
__global__ __launch_bounds__(NTHREADS, 1)
void vq_mma() {
    extern __shared__ float sm[];
    const uint32_t sb = smem_u32(sm);

    const int t = threadIdx.x;
    const int lane = t & 31, wid = t >> 5;
    const int warpM = wid >> 2;          // 0..1
    const int warpN = wid & 3;           // 0..3
    const int g = lane >> 2;             // 0..7
    const int tg = lane & 3;             // 0..3
    const int bid = blockIdx.x;
    const int slot = bid & 3;
    const uint32_t koff_tg = (uint32_t)((tg & 1) * 8 + ((tg >> 1) << 6));
    const uint32_t xorsw = (uint32_t)((tg ^ (g & 3)) << 3);   // bf16 swizzle (bytes)

    // exact-tiling work ranges
    const int itlo = (bid * NITEMS) / NCTA;
    const int ithi = ((bid + 1) * NITEMS) / NCTA;
    const int nsteps = (ithi - itlo) * 8;

    // tf32 loader constants (256 threads: 32 rows x 8 quad-cols per pass)
    const int lr0 = t >> 3;              // 0..31
    const int lqc = t & 7;               // 0..7
    const uint32_t sm_a = (uint32_t)(lr0 * ROWB + lqc * 16);
    const size_t toff = (size_t)lr0 * DDIM + lqc * 4;
    // bf16 loaders: row rH = t>>1 (0..127), half hH = t&1
    const int rH = t >> 1, hH = t & 1;
    const uint32_t dstAB = (uint32_t)(rH * 32 + hH * 16);

    // ---- incremental loader cursors ----
    const int pt0 = itlo >> 5, ch0 = itlo & 31;
    const float*    pAh  = g_zhi + (size_t)pt0 * BM * DDIM + toff;
    const float*    pBh  = g_whi + (size_t)ch0 * BN * DDIM + toff;
    const uint32_t* pZbh = g_zbh + (size_t)(pt0 * BM + rH) * 128 + hH * 4;
    const uint32_t* pZbl = g_zbl + (size_t)(pt0 * BM + rH) * 128 + hH * 4;
    const uint32_t* pWbh = g_wbh + (size_t)(ch0 * BN + rH) * 128 + hH * 4;
    const uint32_t* pWbl = g_wbl + (size_t)(ch0 * BN + rH) * 128 + hH * 4;
    int nextk = 0;                        // float offset within row
    int nchunk = ch0;
    uint32_t lstage = sb;
    int lsgn = STAGE_BYTES;

    auto issue_load = [&]() {
        const uint32_t base = lstage;
        const float* ah = pAh + nextk;
        const float* bh = pBh + nextk;
        const int kw = nextk >> 1;        // packed-word offset
        #pragma unroll
        for (int i = 0; i < 4; i++)
            CP16(base + AH_OFF + sm_a + i * 32 * ROWB, ah + (size_t)i * 32 * DDIM);
        #pragma unroll
        for (int i = 0; i < 8; i++)
            CP16(base + BH_OFF + sm_a + i * 32 * ROWB, bh + (size_t)i * 32 * DDIM);
        #pragma unroll
        for (int b = 0; b < 2; b++) {
            CP16(base + ABH_OFF + b * 4096 + dstAB, pZbh + kw + b * 8);
            CP16(base + ABL_OFF + b * 4096 + dstAB, pZbl + kw + b * 8);
        }
        #pragma unroll
        for (int i = 0; i < 2; i++)
            #pragma unroll
            for (int b = 0; b < 2; b++) {
                CP16(base + BBH_OFF + b * 8192 + dstAB + i * 128 * 32,
                     pWbh + kw + (size_t)i * 128 * 128 + b * 8);
                CP16(base + BBL_OFF + b * 8192 + dstAB + i * 128 * 32,
                     pWbl + kw + (size_t)i * 128 * 128 + b * 8);
            }
        CP_COMMIT();
        lstage += lsgn; lsgn = -lsgn;
        nextk += 32;
        if (nextk == 256) {
            nextk = 0;
            pBh  += (size_t)BN * DDIM;
            pWbh += (size_t)BN * 128;
            pWbl += (size_t)BN * 128;
            if (++nchunk == 32) {
                nchunk = 0;
                pBh  -= (size_t)E_TOTAL * DDIM;
                pWbh -= (size_t)E_TOTAL * 128;
                pWbl -= (size_t)E_TOTAL * 128;
                pAh  += (size_t)BM * DDIM;
                pZbh += (size_t)BM * 128;
                pZbl += (size_t)BM * 128;
            }
        }
    };

    float bestv[4][2];
    int   besti[4][2];
    #pragma unroll
    for (int mi = 0; mi < 4; mi++)
        #pragma unroll
        for (int h = 0; h < 2; h++) { bestv[mi][h] = __int_as_float(0x7f800000); besti[mi][h] = 0; }

    float acc[4][8][4];                   // warp tile 64x64

    issue_load();

    uint32_t cstage = sb;
    int csgn = STAGE_BYTES;

    #pragma unroll 1
    for (int S = 0; S < nsteps; S++) {
        CP_WAIT0();
        __syncthreads();
        if (S + 1 < nsteps) issue_load();

        const int s8 = S & 7;
        if (s8 == 0) {
            #pragma unroll
            for (int mi = 0; mi < 4; mi++)
                #pragma unroll
                for (int ni = 0; ni < 8; ni++)
                    #pragma unroll
                    for (int q = 0; q < 4; q++) acc[mi][ni][q] = 0.0f;
        }

        const uint32_t base = cstage;
        cstage += csgn; csgn = -csgn;

        #pragma unroll
        for (int b = 0; b < 2; b++) {
            // ---- main product: Zh x Wh (tf32, k8 = 2b, 2b+1) ----
            #pragma unroll
            for (int kh = 0; kh < 2; kh++) {
                const uint32_t ko = (uint32_t)((2 * b + kh) * 16) + koff_tg;
                uint2 bh[8];
                #pragma unroll
                for (int ni = 0; ni < 8; ni++)
                    bh[ni] = lds_u64(base + BH_OFF +
                                     (uint32_t)((warpN * 64 + ni * 8 + g) * ROWB) + ko);
                #pragma unroll
                for (int mi = 0; mi < 4; mi++) {
                    const uint32_t ra = (uint32_t)((warpM * 64 + mi * 16 + g) * ROWB) + ko;
                    uint2 aA = lds_u64(base + AH_OFF + ra);
                    uint2 aB = lds_u64(base + AH_OFF + ra + 8 * ROWB);
                    #pragma unroll
                    for (int ni = 0; ni < 8; ni++)
                        mma_tf32(acc[mi][ni][0], acc[mi][ni][1], acc[mi][ni][2], acc[mi][ni][3],
                                 aA.x, aB.x, aA.y, aB.y, bh[ni].x, bh[ni].y);
                }
            }
            // ---- corrections (bf16 m16n8k16, k16-block b) ----
            const uint32_t aboff = (uint32_t)(b * 4096);
            const uint32_t bboff = (uint32_t)(b * 8192);
            // corr1: Zl x Wh
            {
                uint2 wb[8];
                #pragma unroll
                for (int ni = 0; ni < 8; ni++)
                    wb[ni] = lds_u64(base + BBH_OFF + bboff +
                                     (uint32_t)((warpN * 64 + ni * 8 + g) * 32) + xorsw);
                #pragma unroll
                for (int mi = 0; mi < 4; mi++) {
                    const uint32_t ra = aboff +
                        (uint32_t)((warpM * 64 + mi * 16 + g) * 32) + xorsw;
                    uint2 vA = lds_u64(base + ABL_OFF + ra);
                    uint2 vB = lds_u64(base + ABL_OFF + ra + 256);
                    #pragma unroll
                    for (int ni = 0; ni < 8; ni++)
                        mma_bf16(acc[mi][ni][0], acc[mi][ni][1], acc[mi][ni][2], acc[mi][ni][3],
                                 vA.x, vB.x, vA.y, vB.y, wb[ni].x, wb[ni].y);
                }
            }
            // corr2: Zh x Wl
            {
                uint2 wb[8];
                #pragma unroll
                for (int ni = 0; ni < 8; ni++)
                    wb[ni] = lds_u64(base + BBL_OFF + bboff +
                                     (uint32_t)((warpN * 64 + ni * 8 + g) * 32) + xorsw);
                #pragma unroll
                for (int mi = 0; mi < 4; mi++) {
                    const uint32_t ra = aboff +
                        (uint32_t)((warpM * 64 + mi * 16 + g) * 32) + xorsw;
                    uint2 vA = lds_u64(base + ABH_OFF + ra);
                    uint2 vB = lds_u64(base + ABH_OFF + ra + 256);
                    #pragma unroll
                    for (int ni = 0; ni < 8; ni++)
                        mma_bf16(acc[mi][ni][0], acc[mi][ni][1], acc[mi][ni][2], acc[mi][ni][3],
                                 vA.x, vB.x, vA.y, vB.y, wb[ni].x, wb[ni].y);
                }
            }
        }

        if (s8 == 7) {
            const int item = itlo + (S >> 3);
            const int e0 = (item & 31) * BN;
            #pragma unroll
            for (int ni = 0; ni < 8; ni++) {
                const int cl = warpN * 64 + ni * 8 + tg * 2;
                const float2 wq = *(const float2*)&g_wsq[e0 + cl];
                #pragma unroll
                for (int mi = 0; mi < 4; mi++) {
                    #pragma unroll
                    for (int h = 0; h < 2; h++) {
                        float d0 = wq.x - 2.0f * acc[mi][ni][h * 2 + 0];
                        float d1 = wq.y - 2.0f * acc[mi][ni][h * 2 + 1];
                        if (d0 < bestv[mi][h]) { bestv[mi][h] = d0; besti[mi][h] = e0 + cl; }
                        if (d1 < bestv[mi][h]) { bestv[mi][h] = d1; besti[mi][h] = e0 + cl + 1; }
                    }
                }
            }
            const bool last = (S + 1 == nsteps) ||
                              ((itlo + ((S + 1) >> 3)) >> 5) != (item >> 5);
            if (last) {
                const int p0 = (item >> 5) * BM;
                const int c = warpN * 4 + tg;       // 0..15
                #pragma unroll
                for (int mi = 0; mi < 4; mi++)
                    #pragma unroll
                    for (int h = 0; h < 2; h++) {
                        int p = p0 + warpM * 64 + mi * 16 + h * 8 + g;
                        g_pv[slot][p][c] = bestv[mi][h];
                        g_pi[slot][p][c] = besti[mi][h];
                        bestv[mi][h] = __int_as_float(0x7f800000);
                        besti[mi][h] = 0;
                    }
            }
        }
    }
}

// ---------------- Stage C: combine partials, gather z_q, loss partials ----------
__global__ void vq_gather(const float* __restrict__ w, float* __restrict__ out) {
    __shared__ float lsum[256];
    const int t = threadIdx.x;
    const int p = blockIdx.x * 32 + (t >> 3);
    const int j = t & 7;

    // reduce 64 (slot, col) candidates: 8 per thread, then shfl over 8 threads
    float bv = __int_as_float(0x7f800000);
    int bi = 0;
    #pragma unroll
    for (int q = 0; q < 8; q++) {
        int f = j * 8 + q;
        float v = g_pv[f >> 4][p][f & 15];
        int   i = g_pi[f >> 4][p][f & 15];
        if (v < bv || (v == bv && i < bi)) { bv = v; bi = i; }
    }
    #pragma unroll
    for (int off = 4; off >= 1; off >>= 1) {
        float ov = __shfl_down_sync(0xffffffffu, bv, off, 8);
        int   oi = __shfl_down_sync(0xffffffffu, bi, off, 8);
        if (ov < bv || (ov == bv && oi < bi)) { bv = ov; bi = oi; }
    }
    bi = __shfl_sync(0xffffffffu, bi, (t & 31) & ~7);

    const int n = p >> 12;
    const int thw = p & 4095;
    const int obase = n * 1048576 + thw;

    float acc = 0.0f;
    #pragma unroll
    for (int q = 0; q < 8; q++) {
        const int d = j * 32 + q * 4;
        float4 wv = *(const float4*)&w[(size_t)bi * DDIM + d];
        float4 zv = *(const float4*)&g_zl[(size_t)p * DDIM + d];
        out[obase + (d + 0) * 4096] = wv.x;
        out[obase + (d + 1) * 4096] = wv.y;
        out[obase + (d + 2) * 4096] = wv.z;
        out[obase + (d + 3) * 4096] = wv.w;
        float dx = wv.x - zv.x, dy = wv.y - zv.y;
        float dz = wv.z - zv.z, dw = wv.w - zv.w;
        acc += dx*dx + dy*dy + dz*dz + dw*dw;
    }
    if (j == 0) out[IDX_OFF + p] = (float)bi;

    lsum[t] = acc;
    __syncthreads();
    #pragma unroll
    for (int s = 128; s > 0; s >>= 1) {
        if (t < s) lsum[t] += lsum[t + s];
        __syncthreads();
    }
    if (t == 0) g_blockloss[blockIdx.x] = lsum[0];
}

// ---------------- Stage D: deterministic loss reduction ----------------
__global__ void vq_loss(float* __restrict__ out) {
    __shared__ float s[256];
    const int t = threadIdx.x;
    s[t] = g_blockloss[t];
    __syncthreads();
    #pragma unroll
    for (int k = 128; k > 0; k >>= 1) {
        if (t < k) s[t] += s[t + k];
        __syncthreads();
    }
    if (t == 0) out[LOSS_OFF] = 1.25f * s[0] / (float)ZQ_ELEMS;
}

// ---------------- launch ----------------
extern "C" void kernel_launch(void* const* d_in, const int* in_sizes, int n_in,
                              void* d_out, int out_size) {
    const float* z = (const float*)d_in[0];
    const float* w = (const float*)d_in[1];
    float* out = (float*)d_out;

    cudaFuncSetAttribute(vq_mma, cudaFuncAttributeMaxDynamicSharedMemorySize, SMEM_TOTAL);

    vq_prep_z<<<4096, 256>>>(z);
    vq_prep_w<<<4096, 256>>>(w);
    vq_wsq<<<1024, 256>>>(w);
    vq_mma<<<NCTA, NTHREADS, SMEM_TOTAL>>>();
    vq_gather<<<P_TOTAL / 32, 256>>>(w, out);
    vq_loss<<<1, 256>>>(out);
}

// round 12
// speedup vs baseline: 1.3493x; 1.0302x over previous
#include <cuda_runtime.h>
#include <cuda_bf16.h>
#include <cstdint>

// ---------------- problem constants ----------------
#define P_TOTAL 8192
#define DDIM    256
#define E_TOTAL 8192
#define NITEMS  2048                   // 64 ptiles * 32 chunks
#define NCTA    148
#define NSLOT   4

#define ZQ_ELEMS 2097152
#define LOSS_OFF 2097152
#define IDX_OFF  2097153

// ---------------- GEMM tiling ----------------
#define BM 128
#define BN 256
#define BK 32
#define NTHREADS 256
#define TS 36
#define ROWB (TS * 4)                  // 144 B per tf32 smem row
// stage layout (bytes)
#define AH_OFF  0u                     // tf32 Zh: 128 x 144      = 18432
#define BH_OFF  18432u                 // tf32 Wh: 256 x 144      = 36864
#define ABH_OFF 55296u                 // bf16 Zh: 2 x 128 x 32   = 8192
#define ABL_OFF 63488u                 // bf16 Zl: 8192
#define BBH_OFF 71680u                 // bf16 Wh: 2 x 256 x 32   = 16384
#define BBL_OFF 88064u                 // bf16 Wl: 16384
#define STAGE_BYTES 104448
#define SMEM_TOTAL (2 * STAGE_BYTES)   // 208896

// ---------------- scratch ----------------
__device__ __align__(256) float    g_zhi[P_TOTAL * DDIM];    // tf32, k-permuted
__device__ __align__(256) float    g_zl [P_TOTAL * DDIM];    // plain [p][d]
__device__ __align__(256) uint32_t g_zbh[P_TOTAL * DDIM/2];  // bf16 pairs, swizzled
__device__ __align__(256) uint32_t g_zbl[P_TOTAL * DDIM/2];
__device__ __align__(256) float    g_whi[E_TOTAL * DDIM];    // tf32, k-permuted
__device__ __align__(256) uint32_t g_wbh[E_TOTAL * DDIM/2];
__device__ __align__(256) uint32_t g_wbl[E_TOTAL * DDIM/2];
__device__ __align__(256) float    g_wsq[E_TOTAL];
__device__ float g_pv[NSLOT][P_TOTAL][16];
__device__ int   g_pi[NSLOT][P_TOTAL][16];
__device__ float g_blockloss[256];

// ---------------- helpers ----------------
__device__ __forceinline__ uint32_t smem_u32(const void* p) {
    uint32_t a;
    asm("{ .reg .u64 t; cvta.to.shared.u64 t, %1; cvt.u32.u64 %0, t; }" : "=r"(a) : "l"(p));
    return a;
}
#define CP16(sa, ga) \
    asm volatile("cp.async.cg.shared.global [%0], [%1], 16;" :: "r"((uint32_t)(sa)), "l"(ga))
#define CP_COMMIT() asm volatile("cp.async.commit_group;" ::: "memory")
#define CP_WAIT0()  asm volatile("cp.async.wait_group 0;" ::: "memory")

__device__ __forceinline__ float tf32r(float x) {
    uint32_t r;
    asm("cvt.rna.tf32.f32 %0, %1;" : "=r"(r) : "f"(x));
    return __uint_as_float(r);
}
__device__ __forceinline__ uint2 lds_u64(uint32_t addr) {
    uint2 v;
    asm volatile("ld.shared.v2.b32 {%0,%1}, [%2];" : "=r"(v.x), "=r"(v.y) : "r"(addr));
    return v;
}
__device__ __forceinline__ void mma_tf32(float& c0, float& c1, float& c2, float& c3,
                                         uint32_t a0, uint32_t a1, uint32_t a2, uint32_t a3,
                                         uint32_t b0, uint32_t b1) {
    asm volatile("mma.sync.aligned.m16n8k8.row.col.f32.tf32.tf32.f32 "
                 "{%0,%1,%2,%3}, {%4,%5,%6,%7}, {%8,%9}, {%0,%1,%2,%3};"
                 : "+f"(c0), "+f"(c1), "+f"(c2), "+f"(c3)
                 : "r"(a0), "r"(a1), "r"(a2), "r"(a3), "r"(b0), "r"(b1));
}
__device__ __forceinline__ void mma_bf16(float& c0, float& c1, float& c2, float& c3,
                                         uint32_t a0, uint32_t a1, uint32_t a2, uint32_t a3,
                                         uint32_t b0, uint32_t b1) {
    asm volatile("mma.sync.aligned.m16n8k16.row.col.f32.bf16.bf16.f32 "
                 "{%0,%1,%2,%3}, {%4,%5,%6,%7}, {%8,%9}, {%0,%1,%2,%3};"
                 : "+f"(c0), "+f"(c1), "+f"(c2), "+f"(c3)
                 : "r"(a0), "r"(a1), "r"(a2), "r"(a3), "r"(b0), "r"(b1));
}
// tf32 conflict-free permutation (validated R9)
__device__ __forceinline__ int dperm(int d) {
    int blk = d & ~31;
    int kk = d & 31;
    int b = kk >> 3;
    int tg = kk & 3;
    int c = (kk >> 2) & 1;
    return blk + (tg & 1) * 2 + ((tg >> 1) << 4) + (b << 2) + c;
}
__device__ __forceinline__ uint32_t packbf2(float lo, float hi) {
    __nv_bfloat162 v = __floats2bfloat162_rn(lo, hi);
    return *reinterpret_cast<uint32_t*>(&v);
}
// bf16 packed word index within a row (128 words)
__device__ __forceinline__ int bfwidx(int d0, int r) {
    int kb = d0 >> 4;
    int kk = d0 & 15;
    int pr = (kk >> 1) & 3;
    int c  = kk >> 3;
    return kb * 8 + ((pr ^ (r & 3)) << 1) + c;
}

// ---------------- pipelined segment helpers --------------------------------
// segment S (0..7): b = S>>2 ; (S&2)==0 -> tf32 (kh=S&1) ; else bf16 corr (c=S&1)
// corr c=0: A=Zl(ABL), B=Wh(BBH) ; c=1: A=Zh(ABH), B=Wl(BBL)
template<int S>
__device__ __forceinline__ void load_seg(uint32_t base, uint32_t oAH, uint32_t oBH,
                                         uint32_t oCA, uint32_t oCB,
                                         uint2* fa, uint2* fb) {
    constexpr int b = S >> 2;
    if constexpr ((S & 2) == 0) {
        constexpr uint32_t ko = (uint32_t)((2 * b + (S & 1)) * 16);
        #pragma unroll
        for (int ni = 0; ni < 8; ni++)
            fb[ni] = lds_u64(base + oBH + (uint32_t)(ni * 8 * ROWB) + ko);
        #pragma unroll
        for (int mi = 0; mi < 4; mi++) {
            fa[2*mi]   = lds_u64(base + oAH + (uint32_t)(mi * 16 * ROWB) + ko);
            fa[2*mi+1] = lds_u64(base + oAH + (uint32_t)(mi * 16 * ROWB + 8 * ROWB) + ko);
        }
    } else {
        constexpr int c = S & 1;
        constexpr uint32_t bb = (c ? BBL_OFF : BBH_OFF) + (uint32_t)(b * 8192);
        constexpr uint32_t ab = (c ? ABH_OFF : ABL_OFF) + (uint32_t)(b * 4096);
        #pragma unroll
        for (int ni = 0; ni < 8; ni++)
            fb[ni] = lds_u64(base + bb + oCB + (uint32_t)(ni * 256));
        #pragma unroll
        for (int mi = 0; mi < 4; mi++) {
            fa[2*mi]   = lds_u64(base + ab + oCA + (uint32_t)(mi * 512));
            fa[2*mi+1] = lds_u64(base + ab + oCA + (uint32_t)(mi * 512 + 256));
        }
    }
}
template<int S>
__device__ __forceinline__ void mma_seg(float (&acc)[4][8][4],
                                        const uint2* fa, const uint2* fb) {
    #pragma unroll
    for (int mi = 0; mi < 4; mi++)
        #pragma unroll
        for (int ni = 0; ni < 8; ni++) {
            if constexpr ((S & 2) == 0)
                mma_tf32(acc[mi][ni][0], acc[mi][ni][1], acc[mi][ni][2], acc[mi][ni][3],
                         fa[2*mi].x, fa[2*mi+1].x, fa[2*mi].y, fa[2*mi+1].y,
                         fb[ni].x, fb[ni].y);
            else
                mma_bf16(acc[mi][ni][0], acc[mi][ni][1], acc[mi][ni][2], acc[mi][ni][3],
                         fa[2*mi].x, fa[2*mi+1].x, fa[2*mi].y, fa[2*mi+1].y,
                         fb[ni].x, fb[ni].y);
        }
}

// ---------------- Stage A1: z -> tf32 hi + bf16 (hi,lo) + plain + partial init --
__global__ void vq_prep_z(const float* __restrict__ z) {
    int idx = blockIdx.x * 256 + threadIdx.x;   // 0..1048575
    int n = idx >> 19;
    int rem = idx & 524287;
    int dp = rem >> 12;        // 0..127
    int thw = rem & 4095;
    int d0 = dp * 2;
    float v0 = z[((n << 8) + d0) * 4096 + thw];
    float v1 = z[((n << 8) + d0 + 1) * 4096 + thw];
    int p = (n << 12) + thw;
    float h0 = tf32r(v0), h1 = tf32r(v1);
    g_zhi[p * DDIM + dperm(d0)]     = h0;
    g_zhi[p * DDIM + dperm(d0 + 1)] = h1;
    g_zl[p * DDIM + d0]     = v0;
    g_zl[p * DDIM + d0 + 1] = v1;
    int wi = p * 128 + bfwidx(d0, p);
    g_zbh[wi] = packbf2(h0, h1);
    g_zbl[wi] = packbf2(v0 - h0, v1 - h1);
    if (idx < NSLOT * P_TOTAL * 16) {
        ((float*)g_pv)[idx] = __int_as_float(0x7f800000);
        ((int*)g_pi)[idx] = 0;
    }
}

// ---------------- Stage A2: w -> tf32 hi + bf16 (hi,lo) ----------------
__global__ void vq_prep_w(const float* __restrict__ w) {
    int idx = blockIdx.x * 256 + threadIdx.x;   // 0..1048575
    int e = idx >> 7;
    int dp = idx & 127;
    int d0 = dp * 2;
    float v0 = w[e * DDIM + d0];
    float v1 = w[e * DDIM + d0 + 1];
    float h0 = tf32r(v0), h1 = tf32r(v1);
    g_whi[e * DDIM + dperm(d0)]     = h0;
    g_whi[e * DDIM + dperm(d0 + 1)] = h1;
    int wi = e * 128 + bfwidx(d0, e);
    g_wbh[wi] = packbf2(h0, h1);
    g_wbl[wi] = packbf2(v0 - h0, v1 - h1);
}

// ---------------- Stage A3: ||w_e||^2 ----------------
__global__ void vq_wsq(const float* __restrict__ w) {
    int gwarp = (blockIdx.x * blockDim.x + threadIdx.x) >> 5;
    int lane = threadIdx.x & 31;
    const float* row = w + (size_t)gwarp * DDIM;
    float4 a = *(const float4*)&row[lane * 4];
    float4 b = *(const float4*)&row[128 + lane * 4];
    float s = a.x*a.x + a.y*a.y + a.z*a.z + a.w*a.w
            + b.x*b.x + b.y*b.y + b.z*b.z + b.w*b.w;
    #pragma unroll
    for (int off = 16; off >= 1; off >>= 1)
        s += __shfl_down_sync(0xffffffffu, s, off);
    if (lane == 0) g_wsq[gwarp] = s;
}

// ---------------- Stage B: persistent tf32+bf16 distance GEMM + argmin --------
__global__ __launch_bounds__(NTHREADS, 1)
void vq_mma() {
    extern __shared__ float sm[];
    const uint32_t sb = smem_u32(sm);

    const int t = threadIdx.x;
    const int lane = t & 31, wid = t >> 5;
    const int warpM = wid >> 2;          // 0..1
    const int warpN = wid & 3;           // 0..3
    const int g = lane >> 2;             // 0..7
    const int tg = lane & 3;             // 0..3
    const int bid = blockIdx.x;
    const int slot = bid & 3;
    const uint32_t koff_tg = (uint32_t)((tg & 1) * 8 + ((tg >> 1) << 6));
    const uint32_t xorsw = (uint32_t)((tg ^ (g & 3)) << 3);   // bf16 swizzle (bytes)

    // per-warp fragment base offsets (relative to stage base)
    const uint32_t oAH = AH_OFF + (uint32_t)((warpM * 64 + g) * ROWB) + koff_tg;
    const uint32_t oBH = BH_OFF + (uint32_t)((warpN * 64 + g) * ROWB) + koff_tg;
    const uint32_t oCA = (uint32_t)((warpM * 64 + g) * 32) + xorsw;
    const uint32_t oCB = (uint32_t)((warpN * 64 + g) * 32) + xorsw;

    // exact-tiling work ranges
    const int itlo = (bid * NITEMS) / NCTA;
    const int ithi = ((bid + 1) * NITEMS) / NCTA;
    const int nsteps = (ithi - itlo) * 8;

    // tf32 loader constants (256 threads: 32 rows x 8 quad-cols per pass)
    const int lr0 = t >> 3;              // 0..31
    const int lqc = t & 7;               // 0..7
    const uint32_t sm_a = (uint32_t)(lr0 * ROWB + lqc * 16);
    const size_t toff = (size_t)lr0 * DDIM + lqc * 4;
    // bf16 loaders: row rH = t>>1 (0..127), half hH = t&1
    const int rH = t >> 1, hH = t & 1;
    const uint32_t dstAB = (uint32_t)(rH * 32 + hH * 16);

    // ---- incremental loader cursors ----
    const int pt0 = itlo >> 5, ch0 = itlo & 31;
    const float*    pAh  = g_zhi + (size_t)pt0 * BM * DDIM + toff;
    const float*    pBh  = g_whi + (size_t)ch0 * BN * DDIM + toff;
    const uint32_t* pZbh = g_zbh + (size_t)(pt0 * BM + rH) * 128 + hH * 4;
    const uint32_t* pZbl = g_zbl + (size_t)(pt0 * BM + rH) * 128 + hH * 4;
    const uint32_t* pWbh = g_wbh + (size_t)(ch0 * BN + rH) * 128 + hH * 4;
    const uint32_t* pWbl = g_wbl + (size_t)(ch0 * BN + rH) * 128 + hH * 4;
    int nextk = 0;                        // float offset within row
    int nchunk = ch0;
    uint32_t lstage = sb;
    int lsgn = STAGE_BYTES;

    auto issue_load = [&]() {
        const uint32_t base = lstage;
        const float* ah = pAh + nextk;
        const float* bh = pBh + nextk;
        const int kw = nextk >> 1;        // packed-word offset
        #pragma unroll
        for (int i = 0; i < 4; i++)
            CP16(base + AH_OFF + sm_a + i * 32 * ROWB, ah + (size_t)i * 32 * DDIM);
        #pragma unroll
        for (int i = 0; i < 8; i++)
            CP16(base + BH_OFF + sm_a + i * 32 * ROWB, bh + (size_t)i * 32 * DDIM);
        #pragma unroll
        for (int b = 0; b < 2; b++) {
            CP16(base + ABH_OFF + b * 4096 + dstAB, pZbh + kw + b * 8);
            CP16(base + ABL_OFF + b * 4096 + dstAB, pZbl + kw + b * 8);
        }
        #pragma unroll
        for (int i = 0; i < 2; i++)
            #pragma unroll
            for (int b = 0; b < 2; b++) {
                CP16(base + BBH_OFF + b * 8192 + dstAB + i * 128 * 32,
                     pWbh + kw + (size_t)i * 128 * 128 + b * 8);
                CP16(base + BBL_OFF + b * 8192 + dstAB + i * 128 * 32,
                     pWbl + kw + (size_t)i * 128 * 128 + b * 8);
            }
        CP_COMMIT();
        lstage += lsgn; lsgn = -lsgn;
        nextk += 32;
        if (nextk == 256) {
            nextk = 0;
            pBh  += (size_t)BN * DDIM;
            pWbh += (size_t)BN * 128;
            pWbl += (size_t)BN * 128;
            if (++nchunk == 32) {
                nchunk = 0;
                pBh  -= (size_t)E_TOTAL * DDIM;
                pWbh -= (size_t)E_TOTAL * 128;
                pWbl -= (size_t)E_TOTAL * 128;
                pAh  += (size_t)BM * DDIM;
                pZbh += (size_t)BM * 128;
                pZbl += (size_t)BM * 128;
            }
        }
    };

    float bestv[4][2];
    int   besti[4][2];
    #pragma unroll
    for (int mi = 0; mi < 4; mi++)
        #pragma unroll
        for (int h = 0; h < 2; h++) { bestv[mi][h] = __int_as_float(0x7f800000); besti[mi][h] = 0; }

    float acc[4][8][4];                   // warp tile 64x64

    issue_load();

    uint32_t cstage = sb;
    int csgn = STAGE_BYTES;

    #pragma unroll 1
    for (int S = 0; S < nsteps; S++) {
        CP_WAIT0();
        __syncthreads();

        const int s8 = S & 7;
        if (s8 == 0) {
            #pragma unroll
            for (int mi = 0; mi < 4; mi++)
                #pragma unroll
                for (int ni = 0; ni < 8; ni++)
                    #pragma unroll
                    for (int q = 0; q < 4; q++) acc[mi][ni][q] = 0.0f;
        }

        const uint32_t base = cstage;
        cstage += csgn; csgn = -csgn;

        // ---- software-pipelined 8-segment step (double-buffered fragments) ----
        uint2 fA[2][8], fB[2][8];
        load_seg<0>(base, oAH, oBH, oCA, oCB, fA[0], fB[0]);
        load_seg<1>(base, oAH, oBH, oCA, oCB, fA[1], fB[1]);
        mma_seg<0>(acc, fA[0], fB[0]);
        if (S + 1 < nsteps) issue_load();     // off the step-start critical path
        load_seg<2>(base, oAH, oBH, oCA, oCB, fA[0], fB[0]);
        mma_seg<1>(acc, fA[1], fB[1]);
        load_seg<3>(base, oAH, oBH, oCA, oCB, fA[1], fB[1]);
        mma_seg<2>(acc, fA[0], fB[0]);
        load_seg<4>(base, oAH, oBH, oCA, oCB, fA[0], fB[0]);
        mma_seg<3>(acc, fA[1], fB[1]);
        load_seg<5>(base, oAH, oBH, oCA, oCB, fA[1], fB[1]);
        mma_seg<4>(acc, fA[0], fB[0]);
        load_seg<6>(base, oAH, oBH, oCA, oCB, fA[0], fB[0]);
        mma_seg<5>(acc, fA[1], fB[1]);
        load_seg<7>(base, oAH, oBH, oCA, oCB, fA[1], fB[1]);
        mma_seg<6>(acc, fA[0], fB[0]);
        mma_seg<7>(acc, fA[1], fB[1]);

        if (s8 == 7) {
            const int item = itlo + (S >> 3);
            const int e0 = (item & 31) * BN;
            #pragma unroll
            for (int ni = 0; ni < 8; ni++) {
                const int cl = warpN * 64 + ni * 8 + tg * 2;
                const float2 wq = *(const float2*)&g_wsq[e0 + cl];
                #pragma unroll
                for (int mi = 0; mi < 4; mi++) {
                    #pragma unroll
                    for (int h = 0; h < 2; h++) {
                        float d0 = wq.x - 2.0f * acc[mi][ni][h * 2 + 0];
                        float d1 = wq.y - 2.0f * acc[mi][ni][h * 2 + 1];
                        if (d0 < bestv[mi][h]) { bestv[mi][h] = d0; besti[mi][h] = e0 + cl; }
                        if (d1 < bestv[mi][h]) { bestv[mi][h] = d1; besti[mi][h] = e0 + cl + 1; }
                    }
                }
            }
            const bool last = (S + 1 == nsteps) ||
                              ((itlo + ((S + 1) >> 3)) >> 5) != (item >> 5);
            if (last) {
                const int p0 = (item >> 5) * BM;
                const int c = warpN * 4 + tg;       // 0..15
                #pragma unroll
                for (int mi = 0; mi < 4; mi++)
                    #pragma unroll
                    for (int h = 0; h < 2; h++) {
                        int p = p0 + warpM * 64 + mi * 16 + h * 8 + g;
                        g_pv[slot][p][c] = bestv[mi][h];
                        g_pi[slot][p][c] = besti[mi][h];
                        bestv[mi][h] = __int_as_float(0x7f800000);
                        besti[mi][h] = 0;
                    }
            }
        }
    }
}

// ---------------- Stage C: combine partials, gather z_q, loss partials ----------
__global__ void vq_gather(const float* __restrict__ w, float* __restrict__ out) {
    __shared__ float lsum[256];
    const int t = threadIdx.x;
    const int p = blockIdx.x * 32 + (t >> 3);
    const int j = t & 7;

    // reduce 64 (slot, col) candidates: 8 per thread, then shfl over 8 threads
    float bv = __int_as_float(0x7f800000);
    int bi = 0;
    #pragma unroll
    for (int q = 0; q < 8; q++) {
        int f = j * 8 + q;
        float v = g_pv[f >> 4][p][f & 15];
        int   i = g_pi[f >> 4][p][f & 15];
        if (v < bv || (v == bv && i < bi)) { bv = v; bi = i; }
    }
    #pragma unroll
    for (int off = 4; off >= 1; off >>= 1) {
        float ov = __shfl_down_sync(0xffffffffu, bv, off, 8);
        int   oi = __shfl_down_sync(0xffffffffu, bi, off, 8);
        if (ov < bv || (ov == bv && oi < bi)) { bv = ov; bi = oi; }
    }
    bi = __shfl_sync(0xffffffffu, bi, (t & 31) & ~7);

    const int n = p >> 12;
    const int thw = p & 4095;
    const int obase = n * 1048576 + thw;

    float acc = 0.0f;
    #pragma unroll
    for (int q = 0; q < 8; q++) {
        const int d = j * 32 + q * 4;
        float4 wv = *(const float4*)&w[(size_t)bi * DDIM + d];
        float4 zv = *(const float4*)&g_zl[(size_t)p * DDIM + d];
        out[obase + (d + 0) * 4096] = wv.x;
        out[obase + (d + 1) * 4096] = wv.y;
        out[obase + (d + 2) * 4096] = wv.z;
        out[obase + (d + 3) * 4096] = wv.w;
        float dx = wv.x - zv.x, dy = wv.y - zv.y;
        float dz = wv.z - zv.z, dw = wv.w - zv.w;
        acc += dx*dx + dy*dy + dz*dz + dw*dw;
    }
    if (j == 0) out[IDX_OFF + p] = (float)bi;

    lsum[t] = acc;
    __syncthreads();
    #pragma unroll
    for (int s = 128; s > 0; s >>= 1) {
        if (t < s) lsum[t] += lsum[t + s];
        __syncthreads();
    }
    if (t == 0) g_blockloss[blockIdx.x] = lsum[0];
}

// ---------------- Stage D: deterministic loss reduction ----------------
__global__ void vq_loss(float* __restrict__ out) {
    __shared__ float s[256];
    const int t = threadIdx.x;
    s[t] = g_blockloss[t];
    __syncthreads();
    #pragma unroll
    for (int k = 128; k > 0; k >>= 1) {
        if (t < k) s[t] += s[t + k];
        __syncthreads();
    }
    if (t == 0) out[LOSS_OFF] = 1.25f * s[0] / (float)ZQ_ELEMS;
}

// ---------------- launch ----------------
extern "C" void kernel_launch(void* const* d_in, const int* in_sizes, int n_in,
                              void* d_out, int out_size) {
    const float* z = (const float*)d_in[0];
    const float* w = (const float*)d_in[1];
    float* out = (float*)d_out;

    cudaFuncSetAttribute(vq_mma, cudaFuncAttributeMaxDynamicSharedMemorySize, SMEM_TOTAL);

    vq_prep_z<<<4096, 256>>>(z);
    vq_prep_w<<<4096, 256>>>(w);
    vq_wsq<<<1024, 256>>>(w);
    vq_mma<<<NCTA, NTHREADS, SMEM_TOTAL>>>();
    vq_gather<<<P_TOTAL / 32, 256>>>(w, out);
    vq_loss<<<1, 256>>>(out);
}

// round 13
// speedup vs baseline: 1.4577x; 1.0804x over previous
#include <cuda_runtime.h>
#include <cuda_bf16.h>
#include <cstdint>

// ---------------- problem constants ----------------
#define P_TOTAL 8192
#define DDIM    256
#define E_TOTAL 8192
#define NITEMS  2048                   // 64 ptiles * 32 chunks
#define NCTA    148
#define NSLOT   4

#define ZQ_ELEMS 2097152
#define LOSS_OFF 2097152
#define IDX_OFF  2097153

// ---------------- GEMM tiling ----------------
#define BM 128
#define BN 256
#define BK 32
#define NTHREADS 256
#define TS 36
#define ROWB (TS * 4)                  // 144 B per tf32 smem row
// stage layout (bytes)
#define AH_OFF  0u                     // tf32 Zh: 128 x 144      = 18432
#define BH_OFF  18432u                 // tf32 Wh: 256 x 144      = 36864
#define ABH_OFF 55296u                 // bf16 Zh: 2 x 128 x 32   = 8192
#define ABL_OFF 63488u                 // bf16 Zl: 8192
#define BBH_OFF 71680u                 // bf16 Wh: 2 x 256 x 32   = 16384
#define BBL_OFF 88064u                 // bf16 Wl: 16384
#define STAGE_BYTES 104448
#define SMEM_TOTAL (2 * STAGE_BYTES)   // 208896

// ---------------- scratch ----------------
__device__ __align__(256) float    g_zhi[P_TOTAL * DDIM];    // tf32, k-permuted
__device__ __align__(256) float    g_zl [P_TOTAL * DDIM];    // plain [p][d]
__device__ __align__(256) uint32_t g_zbh[P_TOTAL * DDIM/2];  // bf16 pairs, swizzled
__device__ __align__(256) uint32_t g_zbl[P_TOTAL * DDIM/2];
__device__ __align__(256) float    g_whi[E_TOTAL * DDIM];    // tf32, k-permuted
__device__ __align__(256) uint32_t g_wbh[E_TOTAL * DDIM/2];
__device__ __align__(256) uint32_t g_wbl[E_TOTAL * DDIM/2];
__device__ __align__(256) float    g_wsq[E_TOTAL];
__device__ float g_pv[NSLOT][P_TOTAL][16];
__device__ int   g_pi[NSLOT][P_TOTAL][16];
__device__ float g_blockloss[256];

// ---------------- helpers ----------------
__device__ __forceinline__ uint32_t smem_u32(const void* p) {
    uint32_t a;
    asm("{ .reg .u64 t; cvta.to.shared.u64 t, %1; cvt.u32.u64 %0, t; }" : "=r"(a) : "l"(p));
    return a;
}
#define CP16(sa, ga) \
    asm volatile("cp.async.cg.shared.global [%0], [%1], 16;" :: "r"((uint32_t)(sa)), "l"(ga))
#define CP_COMMIT() asm volatile("cp.async.commit_group;" ::: "memory")
#define CP_WAIT0()  asm volatile("cp.async.wait_group 0;" ::: "memory")

__device__ __forceinline__ float tf32r(float x) {
    uint32_t r;
    asm("cvt.rna.tf32.f32 %0, %1;" : "=r"(r) : "f"(x));
    return __uint_as_float(r);
}
__device__ __forceinline__ uint2 lds_u64(uint32_t addr) {
    uint2 v;
    asm volatile("ld.shared.v2.b32 {%0,%1}, [%2];" : "=r"(v.x), "=r"(v.y) : "r"(addr));
    return v;
}
__device__ __forceinline__ void mma_tf32(float& c0, float& c1, float& c2, float& c3,
                                         uint32_t a0, uint32_t a1, uint32_t a2, uint32_t a3,
                                         uint32_t b0, uint32_t b1) {
    asm volatile("mma.sync.aligned.m16n8k8.row.col.f32.tf32.tf32.f32 "
                 "{%0,%1,%2,%3}, {%4,%5,%6,%7}, {%8,%9}, {%0,%1,%2,%3};"
                 : "+f"(c0), "+f"(c1), "+f"(c2), "+f"(c3)
                 : "r"(a0), "r"(a1), "r"(a2), "r"(a3), "r"(b0), "r"(b1));
}
__device__ __forceinline__ void mma_bf16(float& c0, float& c1, float& c2, float& c3,
                                         uint32_t a0, uint32_t a1, uint32_t a2, uint32_t a3,
                                         uint32_t b0, uint32_t b1) {
    asm volatile("mma.sync.aligned.m16n8k16.row.col.f32.bf16.bf16.f32 "
                 "{%0,%1,%2,%3}, {%4,%5,%6,%7}, {%8,%9}, {%0,%1,%2,%3};"
                 : "+f"(c0), "+f"(c1), "+f"(c2), "+f"(c3)
                 : "r"(a0), "r"(a1), "r"(a2), "r"(a3), "r"(b0), "r"(b1));
}
// tf32 conflict-free permutation (validated R9)
__device__ __forceinline__ int dperm(int d) {
    int blk = d & ~31;
    int kk = d & 31;
    int b = kk >> 3;
    int tg = kk & 3;
    int c = (kk >> 2) & 1;
    return blk + (tg & 1) * 2 + ((tg >> 1) << 4) + (b << 2) + c;
}
__device__ __forceinline__ uint32_t packbf2(float lo, float hi) {
    __nv_bfloat162 v = __floats2bfloat162_rn(lo, hi);
    return *reinterpret_cast<uint32_t*>(&v);
}
// bf16 packed word index within a row (128 words)
__device__ __forceinline__ int bfwidx(int d0, int r) {
    int kb = d0 >> 4;
    int kk = d0 & 15;
    int pr = (kk >> 1) & 3;
    int c  = kk >> 3;
    return kb * 8 + ((pr ^ (r & 3)) << 1) + c;
}

// ---------------- per-element segment loaders / mma -------------------------
// segment S (0..7): b = S>>2 ; (S&2)==0 -> tf32 (kh=S&1) ; else bf16 corr (c=S&1)
// corr c=0: A=Zl(ABL), B=Wh(BBH) ; c=1: A=Zh(ABH), B=Wl(BBL)
template<int S>
__device__ __forceinline__ uint2 load_b_i(uint32_t base, uint32_t oBH, uint32_t oCB, int ni) {
    constexpr int b = S >> 2;
    if constexpr ((S & 2) == 0) {
        constexpr uint32_t ko = (uint32_t)((2 * b + (S & 1)) * 16);
        return lds_u64(base + oBH + (uint32_t)(ni * 8 * ROWB) + ko);
    } else {
        constexpr int c = S & 1;
        constexpr uint32_t bb = (c ? BBL_OFF : BBH_OFF) + (uint32_t)(b * 8192);
        return lds_u64(base + bb + oCB + (uint32_t)(ni * 256));
    }
}
template<int S>
__device__ __forceinline__ uint2 load_a_i(uint32_t base, uint32_t oAH, uint32_t oCA, int q) {
    constexpr int b = S >> 2;
    const int mi = q >> 1, half = q & 1;
    if constexpr ((S & 2) == 0) {
        constexpr uint32_t ko = (uint32_t)((2 * b + (S & 1)) * 16);
        return lds_u64(base + oAH + (uint32_t)((mi * 16 + half * 8) * ROWB) + ko);
    } else {
        constexpr int c = S & 1;
        constexpr uint32_t ab = (c ? ABH_OFF : ABL_OFF) + (uint32_t)(b * 4096);
        return lds_u64(base + ab + oCA + (uint32_t)(mi * 512 + half * 256));
    }
}
template<int S>
__device__ __forceinline__ void mma_i(float (&acc)[4][8][4], const uint2* fa, const uint2* fb, int j) {
    const int mi = j >> 3, ni = j & 7;
    if constexpr ((S & 2) == 0)
        mma_tf32(acc[mi][ni][0], acc[mi][ni][1], acc[mi][ni][2], acc[mi][ni][3],
                 fa[2*mi].x, fa[2*mi+1].x, fa[2*mi].y, fa[2*mi+1].y, fb[ni].x, fb[ni].y);
    else
        mma_bf16(acc[mi][ni][0], acc[mi][ni][1], acc[mi][ni][2], acc[mi][ni][3],
                 fa[2*mi].x, fa[2*mi+1].x, fa[2*mi].y, fa[2*mi+1].y, fb[ni].x, fb[ni].y);
}
template<int S>
__device__ __forceinline__ void load_full(uint32_t base, uint32_t oAH, uint32_t oBH,
                                          uint32_t oCA, uint32_t oCB, uint2* fa, uint2* fb) {
    #pragma unroll
    for (int i = 0; i < 8; i++) fb[i] = load_b_i<S>(base, oBH, oCB, i);
    #pragma unroll
    for (int i = 0; i < 8; i++) fa[i] = load_a_i<S>(base, oAH, oCA, i);
}
template<int S>
__device__ __forceinline__ void mma_only(float (&acc)[4][8][4], const uint2* fa, const uint2* fb) {
    #pragma unroll
    for (int j = 0; j < 32; j++) mma_i<S>(acc, fa, fb, j);
}
// fine-grained braid: 16 LDS of segment SL woven into the 32 MMAs of segment SM
template<int SL, int SM>
__device__ __forceinline__ void inter(uint32_t base, uint32_t oAH, uint32_t oBH,
                                      uint32_t oCA, uint32_t oCB,
                                      float (&acc)[4][8][4],
                                      uint2* faL, uint2* fbL,
                                      const uint2* faM, const uint2* fbM) {
    #pragma unroll
    for (int i = 0; i < 8; i++) {
        fbL[i] = load_b_i<SL>(base, oBH, oCB, i);
        mma_i<SM>(acc, faM, fbM, 2 * i);
        mma_i<SM>(acc, faM, fbM, 2 * i + 1);
    }
    #pragma unroll
    for (int i = 0; i < 8; i++) {
        faL[i] = load_a_i<SL>(base, oAH, oCA, i);
        mma_i<SM>(acc, faM, fbM, 16 + 2 * i);
        mma_i<SM>(acc, faM, fbM, 17 + 2 * i);
    }
}

// ---------------- Stage A1: z -> tf32 hi + bf16 (hi,lo) + plain + partial init --
__global__ void vq_prep_z(const float* __restrict__ z) {
    int idx = blockIdx.x * 256 + threadIdx.x;   // 0..1048575
    int n = idx >> 19;
    int rem = idx & 524287;
    int dp = rem >> 12;        // 0..127
    int thw = rem & 4095;
    int d0 = dp * 2;
    float v0 = z[((n << 8) + d0) * 4096 + thw];
    float v1 = z[((n << 8) + d0 + 1) * 4096 + thw];
    int p = (n << 12) + thw;
    float h0 = tf32r(v0), h1 = tf32r(v1);
    g_zhi[p * DDIM + dperm(d0)]     = h0;
    g_zhi[p * DDIM + dperm(d0 + 1)] = h1;
    g_zl[p * DDIM + d0]     = v0;
    g_zl[p * DDIM + d0 + 1] = v1;
    int wi = p * 128 + bfwidx(d0, p);
    g_zbh[wi] = packbf2(h0, h1);
    g_zbl[wi] = packbf2(v0 - h0, v1 - h1);
    if (idx < NSLOT * P_TOTAL * 16) {
        ((float*)g_pv)[idx] = __int_as_float(0x7f800000);
        ((int*)g_pi)[idx] = 0;
    }
}

// ---------------- Stage A2: w -> tf32 hi + bf16 (hi,lo) ----------------
__global__ void vq_prep_w(const float* __restrict__ w) {
    int idx = blockIdx.x * 256 + threadIdx.x;   // 0..1048575
    int e = idx >> 7;
    int dp = idx & 127;
    int d0 = dp * 2;
    float v0 = w[e * DDIM + d0];
    float v1 = w[e * DDIM + d0 + 1];
    float h0 = tf32r(v0), h1 = tf32r(v1);
    g_whi[e * DDIM + dperm(d0)]     = h0;
    g_whi[e * DDIM + dperm(d0 + 1)] = h1;
    int wi = e * 128 + bfwidx(d0, e);
    g_wbh[wi] = packbf2(h0, h1);
    g_wbl[wi] = packbf2(v0 - h0, v1 - h1);
}

// ---------------- Stage A3: ||w_e||^2 ----------------
__global__ void vq_wsq(const float* __restrict__ w) {
    int gwarp = (blockIdx.x * blockDim.x + threadIdx.x) >> 5;
    int lane = threadIdx.x & 31;
    const float* row = w + (size_t)gwarp * DDIM;
    float4 a = *(const float4*)&row[lane * 4];
    float4 b = *(const float4*)&row[128 + lane * 4];
    float s = a.x*a.x + a.y*a.y + a.z*a.z + a.w*a.w
            + b.x*b.x + b.y*b.y + b.z*b.z + b.w*b.w;
    #pragma unroll
    for (int off = 16; off >= 1; off >>= 1)
        s += __shfl_down_sync(0xffffffffu, s, off);
    if (lane == 0) g_wsq[gwarp] = s;
}

// ---------------- Stage B: persistent tf32+bf16 distance GEMM + argmin --------
__global__ __launch_bounds__(NTHREADS, 1)
void vq_mma() {
    extern __shared__ float sm[];
    const uint32_t sb = smem_u32(sm);

    const int t = threadIdx.x;
    const int lane = t & 31, wid = t >> 5;
    const int warpM = wid >> 2;          // 0..1
    const int warpN = wid & 3;           // 0..3
    const int g = lane >> 2;             // 0..7
    const int tg = lane & 3;             // 0..3
    const int bid = blockIdx.x;
    const int slot = bid & 3;
    const uint32_t koff_tg = (uint32_t)((tg & 1) * 8 + ((tg >> 1) << 6));
    const uint32_t xorsw = (uint32_t)((tg ^ (g & 3)) << 3);   // bf16 swizzle (bytes)

    // per-warp fragment base offsets (relative to stage base)
    const uint32_t oAH = AH_OFF + (uint32_t)((warpM * 64 + g) * ROWB) + koff_tg;
    const uint32_t oBH = BH_OFF + (uint32_t)((warpN * 64 + g) * ROWB) + koff_tg;
    const uint32_t oCA = (uint32_t)((warpM * 64 + g) * 32) + xorsw;
    const uint32_t oCB = (uint32_t)((warpN * 64 + g) * 32) + xorsw;

    // exact-tiling work ranges
    const int itlo = (bid * NITEMS) / NCTA;
    const int ithi = ((bid + 1) * NITEMS) / NCTA;
    const int nsteps = (ithi - itlo) * 8;

    // tf32 loader constants (256 threads: 32 rows x 8 quad-cols per pass)
    const int lr0 = t >> 3;              // 0..31
    const int lqc = t & 7;               // 0..7
    const uint32_t sm_a = (uint32_t)(lr0 * ROWB + lqc * 16);
    const size_t toff = (size_t)lr0 * DDIM + lqc * 4;
    // bf16 loaders: row rH = t>>1 (0..127), half hH = t&1
    const int rH = t >> 1, hH = t & 1;
    const uint32_t dstAB = (uint32_t)(rH * 32 + hH * 16);

    // ---- incremental loader cursors ----
    const int pt0 = itlo >> 5, ch0 = itlo & 31;
    const float*    pAh  = g_zhi + (size_t)pt0 * BM * DDIM + toff;
    const float*    pBh  = g_whi + (size_t)ch0 * BN * DDIM + toff;
    const uint32_t* pZbh = g_zbh + (size_t)(pt0 * BM + rH) * 128 + hH * 4;
    const uint32_t* pZbl = g_zbl + (size_t)(pt0 * BM + rH) * 128 + hH * 4;
    const uint32_t* pWbh = g_wbh + (size_t)(ch0 * BN + rH) * 128 + hH * 4;
    const uint32_t* pWbl = g_wbl + (size_t)(ch0 * BN + rH) * 128 + hH * 4;
    int nextk = 0;                        // float offset within row
    int nchunk = ch0;
    uint32_t lstage = sb;
    int lsgn = STAGE_BYTES;

    // first half: tf32 tiles (12 cp.async)
    auto issue_load_a = [&]() {
        const uint32_t base = lstage;
        const float* ah = pAh + nextk;
        const float* bh = pBh + nextk;
        #pragma unroll
        for (int i = 0; i < 4; i++)
            CP16(base + AH_OFF + sm_a + i * 32 * ROWB, ah + (size_t)i * 32 * DDIM);
        #pragma unroll
        for (int i = 0; i < 8; i++)
            CP16(base + BH_OFF + sm_a + i * 32 * ROWB, bh + (size_t)i * 32 * DDIM);
    };
    // second half: bf16 tiles (12 cp.async) + commit + cursor advance
    auto issue_load_b = [&]() {
        const uint32_t base = lstage;
        const int kw = nextk >> 1;        // packed-word offset
        #pragma unroll
        for (int b = 0; b < 2; b++) {
            CP16(base + ABH_OFF + b * 4096 + dstAB, pZbh + kw + b * 8);
            CP16(base + ABL_OFF + b * 4096 + dstAB, pZbl + kw + b * 8);
        }
        #pragma unroll
        for (int i = 0; i < 2; i++)
            #pragma unroll
            for (int b = 0; b < 2; b++) {
                CP16(base + BBH_OFF + b * 8192 + dstAB + i * 128 * 32,
                     pWbh + kw + (size_t)i * 128 * 128 + b * 8);
                CP16(base + BBL_OFF + b * 8192 + dstAB + i * 128 * 32,
                     pWbl + kw + (size_t)i * 128 * 128 + b * 8);
            }
        CP_COMMIT();
        lstage += lsgn; lsgn = -lsgn;
        nextk += 32;
        if (nextk == 256) {
            nextk = 0;
            pBh  += (size_t)BN * DDIM;
            pWbh += (size_t)BN * 128;
            pWbl += (size_t)BN * 128;
            if (++nchunk == 32) {
                nchunk = 0;
                pBh  -= (size_t)E_TOTAL * DDIM;
                pWbh -= (size_t)E_TOTAL * 128;
                pWbl -= (size_t)E_TOTAL * 128;
                pAh  += (size_t)BM * DDIM;
                pZbh += (size_t)BM * 128;
                pZbl += (size_t)BM * 128;
            }
        }
    };

    float bestv[4][2];
    int   besti[4][2];
    #pragma unroll
    for (int mi = 0; mi < 4; mi++)
        #pragma unroll
        for (int h = 0; h < 2; h++) { bestv[mi][h] = __int_as_float(0x7f800000); besti[mi][h] = 0; }

    float acc[4][8][4];                   // warp tile 64x64

    issue_load_a();
    issue_load_b();

    uint32_t cstage = sb;
    int csgn = STAGE_BYTES;

    #pragma unroll 1
    for (int S = 0; S < nsteps; S++) {
        CP_WAIT0();
        __syncthreads();

        const int s8 = S & 7;
        if (s8 == 0) {
            #pragma unroll
            for (int mi = 0; mi < 4; mi++)
                #pragma unroll
                for (int ni = 0; ni < 8; ni++)
                    #pragma unroll
                    for (int q = 0; q < 4; q++) acc[mi][ni][q] = 0.0f;
        }

        const uint32_t base = cstage;
        cstage += csgn; csgn = -csgn;
        const bool pf = (S + 1 < nsteps);

        // ---- fine-grained interleaved 8-segment step ----
        uint2 fA[2][8], fB[2][8];
        load_full<0>(base, oAH, oBH, oCA, oCB, fA[0], fB[0]);
        inter<1, 0>(base, oAH, oBH, oCA, oCB, acc, fA[1], fB[1], fA[0], fB[0]);
        if (pf) issue_load_a();
        inter<2, 1>(base, oAH, oBH, oCA, oCB, acc, fA[0], fB[0], fA[1], fB[1]);
        inter<3, 2>(base, oAH, oBH, oCA, oCB, acc, fA[1], fB[1], fA[0], fB[0]);
        if (pf) issue_load_b();
        inter<4, 3>(base, oAH, oBH, oCA, oCB, acc, fA[0], fB[0], fA[1], fB[1]);
        inter<5, 4>(base, oAH, oBH, oCA, oCB, acc, fA[1], fB[1], fA[0], fB[0]);
        inter<6, 5>(base, oAH, oBH, oCA, oCB, acc, fA[0], fB[0], fA[1], fB[1]);
        inter<7, 6>(base, oAH, oBH, oCA, oCB, acc, fA[1], fB[1], fA[0], fB[0]);
        mma_only<7>(acc, fA[1], fB[1]);

        if (s8 == 7) {
            const int item = itlo + (S >> 3);
            const int e0 = (item & 31) * BN;
            #pragma unroll
            for (int ni = 0; ni < 8; ni++) {
                const int cl = warpN * 64 + ni * 8 + tg * 2;
                const float2 wq = *(const float2*)&g_wsq[e0 + cl];
                #pragma unroll
                for (int mi = 0; mi < 4; mi++) {
                    #pragma unroll
                    for (int h = 0; h < 2; h++) {
                        float d0 = wq.x - 2.0f * acc[mi][ni][h * 2 + 0];
                        float d1 = wq.y - 2.0f * acc[mi][ni][h * 2 + 1];
                        if (d0 < bestv[mi][h]) { bestv[mi][h] = d0; besti[mi][h] = e0 + cl; }
                        if (d1 < bestv[mi][h]) { bestv[mi][h] = d1; besti[mi][h] = e0 + cl + 1; }
                    }
                }
            }
            const bool last = (S + 1 == nsteps) ||
                              ((itlo + ((S + 1) >> 3)) >> 5) != (item >> 5);
            if (last) {
                const int p0 = (item >> 5) * BM;
                const int c = warpN * 4 + tg;       // 0..15
                #pragma unroll
                for (int mi = 0; mi < 4; mi++)
                    #pragma unroll
                    for (int h = 0; h < 2; h++) {
                        int p = p0 + warpM * 64 + mi * 16 + h * 8 + g;
                        g_pv[slot][p][c] = bestv[mi][h];
                        g_pi[slot][p][c] = besti[mi][h];
                        bestv[mi][h] = __int_as_float(0x7f800000);
                        besti[mi][h] = 0;
                    }
            }
        }
    }
}

// ---------------- Stage C: combine partials, gather z_q, loss partials ----------
__global__ void vq_gather(const float* __restrict__ w, float* __restrict__ out) {
    __shared__ float lsum[256];
    const int t = threadIdx.x;
    const int p = blockIdx.x * 32 + (t >> 3);
    const int j = t & 7;

    // reduce 64 (slot, col) candidates: 8 per thread, then shfl over 8 threads
    float bv = __int_as_float(0x7f800000);
    int bi = 0;
    #pragma unroll
    for (int q = 0; q < 8; q++) {
        int f = j * 8 + q;
        float v = g_pv[f >> 4][p][f & 15];
        int   i = g_pi[f >> 4][p][f & 15];
        if (v < bv || (v == bv && i < bi)) { bv = v; bi = i; }
    }
    #pragma unroll
    for (int off = 4; off >= 1; off >>= 1) {
        float ov = __shfl_down_sync(0xffffffffu, bv, off, 8);
        int   oi = __shfl_down_sync(0xffffffffu, bi, off, 8);
        if (ov < bv || (ov == bv && oi < bi)) { bv = ov; bi = oi; }
    }
    bi = __shfl_sync(0xffffffffu, bi, (t & 31) & ~7);

    const int n = p >> 12;
    const int thw = p & 4095;
    const int obase = n * 1048576 + thw;

    float acc = 0.0f;
    #pragma unroll
    for (int q = 0; q < 8; q++) {
        const int d = j * 32 + q * 4;
        float4 wv = *(const float4*)&w[(size_t)bi * DDIM + d];
        float4 zv = *(const float4*)&g_zl[(size_t)p * DDIM + d];
        out[obase + (d + 0) * 4096] = wv.x;
        out[obase + (d + 1) * 4096] = wv.y;
        out[obase + (d + 2) * 4096] = wv.z;
        out[obase + (d + 3) * 4096] = wv.w;
        float dx = wv.x - zv.x, dy = wv.y - zv.y;
        float dz = wv.z - zv.z, dw = wv.w - zv.w;
        acc += dx*dx + dy*dy + dz*dz + dw*dw;
    }
    if (j == 0) out[IDX_OFF + p] = (float)bi;

    lsum[t] = acc;
    __syncthreads();
    #pragma unroll
    for (int s = 128; s > 0; s >>= 1) {
        if (t < s) lsum[t] += lsum[t + s];
        __syncthreads();
    }
    if (t == 0) g_blockloss[blockIdx.x] = lsum[0];
}

// ---------------- Stage D: deterministic loss reduction ----------------
__global__ void vq_loss(float* __restrict__ out) {
    __shared__ float s[256];
    const int t = threadIdx.x;
    s[t] = g_blockloss[t];
    __syncthreads();
    #pragma unroll
    for (int k = 128; k > 0; k >>= 1) {
        if (t < k) s[t] += s[t + k];
        __syncthreads();
    }
    if (t == 0) out[LOSS_OFF] = 1.25f * s[0] / (float)ZQ_ELEMS;
}

// ---------------- launch ----------------
extern "C" void kernel_launch(void* const* d_in, const int* in_sizes, int n_in,
                              void* d_out, int out_size) {
    const float* z = (const float*)d_in[0];
    const float* w = (const float*)d_in[1];
    float* out = (float*)d_out;

    cudaFuncSetAttribute(vq_mma, cudaFuncAttributeMaxDynamicSharedMemorySize, SMEM_TOTAL);

    vq_prep_z<<<4096, 256>>>(z);
    vq_prep_w<<<4096, 256>>>(w);
    vq_wsq<<<1024, 256>>>(w);
    vq_mma<<<NCTA, NTHREADS, SMEM_TOTAL>>>();
    vq_gather<<<P_TOTAL / 32, 256>>>(w, out);
    vq_loss<<<1, 256>>>(out);
}